// round 2
// baseline (speedup 1.0000x reference)
#include <cuda_runtime.h>
#include <cstddef>

// ---------------- problem constants ----------------
#define BB   2
#define TT   2048
#define CC   1024
#define NH   16
#define HD   64
#define KVLD 512              // combined K|V row stride
#define MM   (BB * TT)        // 4096
#define ROPE_C 0.14391156831212787f   // ln(10000)/64

// ---------------- scratch ----------------
__device__ float g_q  [MM * CC];      // Q (roped)
__device__ float g_kv [MM * KVLD];    // [K(roped) | V]
__device__ float g_att[MM * CC];      // attention output
__device__ float g_rope[TT * HD];     // per (t, even d): cos at [t*64+d], sin at [t*64+d+1]

// ---------------- rope table ----------------
__global__ void rope_table_kernel()
{
    int t = blockIdx.x;
    int p = threadIdx.x;                  // 0..31
    float inv = expf(-(float)(2 * p) * ROPE_C);
    float sn, cs;
    sincosf((float)t * inv, &sn, &cs);
    g_rope[t * HD + 2 * p]     = cs;
    g_rope[t * HD + 2 * p + 1] = sn;
}

// ---------------- SGEMM 128x128 tile, 8x8 micro, 256 threads ----------------
// C[M,Nout] = A[M,K] @ [W0|W1] + bias, RoPE on cols < rope_until.
// cols < split come from W0 (row stride = split), else W1 (row stride = Nout-split).
__global__ void __launch_bounds__(256, 2)
sgemm128(const float* __restrict__ A,
         const float* __restrict__ W0, const float* __restrict__ b0,
         const float* __restrict__ W1, const float* __restrict__ b1,
         float* __restrict__ C, int K, int Nout, int split, int rope_until)
{
    __shared__ float As[16][132];   // [k][m]
    __shared__ float Bs[16][128];   // [k][n]

    const int tid = threadIdx.x;
    const int tx  = tid & 15;        // col group
    const int ty  = tid >> 4;        // row group
    const int row0 = blockIdx.y * 128;
    const int col0 = blockIdx.x * 128;

    const float* W; const float* bias; int ldw, wc0;
    if (col0 < split) { W = W0; bias = b0; ldw = split;        wc0 = col0;         }
    else              { W = W1; bias = b1; ldw = Nout - split; wc0 = col0 - split; }

    const int am  = tid >> 1;            // 0..127
    const int akq = (tid & 1) * 8;       // 0 or 8
    const int bkk = tid >> 4;            // 0..15
    const int bn  = (tid & 15) * 8;

    const float* Aptr = A + (size_t)(row0 + am) * K + akq;
    const float* Wptr = W + (size_t)bkk * ldw + wc0 + bn;

    float acc[8][8];
    #pragma unroll
    for (int i = 0; i < 8; i++)
        #pragma unroll
        for (int j = 0; j < 8; j++) acc[i][j] = 0.f;

    for (int k0 = 0; k0 < K; k0 += 16) {
        float4 a0 = *(const float4*)(Aptr + k0);
        float4 a1 = *(const float4*)(Aptr + k0 + 4);
        float4 w0 = *(const float4*)(Wptr + (size_t)k0 * ldw);
        float4 w1 = *(const float4*)(Wptr + (size_t)k0 * ldw + 4);

        As[akq + 0][am] = a0.x; As[akq + 1][am] = a0.y;
        As[akq + 2][am] = a0.z; As[akq + 3][am] = a0.w;
        As[akq + 4][am] = a1.x; As[akq + 5][am] = a1.y;
        As[akq + 6][am] = a1.z; As[akq + 7][am] = a1.w;
        *(float4*)&Bs[bkk][bn]     = w0;
        *(float4*)&Bs[bkk][bn + 4] = w1;
        __syncthreads();

        #pragma unroll
        for (int kk = 0; kk < 16; kk++) {
            float a[8], b[8];
            *(float4*)&a[0] = *(const float4*)&As[kk][ty * 8];
            *(float4*)&a[4] = *(const float4*)&As[kk][ty * 8 + 4];
            *(float4*)&b[0] = *(const float4*)&Bs[kk][tx * 8];
            *(float4*)&b[4] = *(const float4*)&Bs[kk][tx * 8 + 4];
            #pragma unroll
            for (int i = 0; i < 8; i++)
                #pragma unroll
                for (int j = 0; j < 8; j++)
                    acc[i][j] = fmaf(a[i], b[j], acc[i][j]);
        }
        __syncthreads();
    }

    // epilogue: bias (+ RoPE via table)
    const bool rope = (col0 < rope_until);
    #pragma unroll
    for (int i = 0; i < 8; i++) {
        const int r = row0 + ty * 8 + i;
        const int t = r & (TT - 1);
        float o8[8];
        #pragma unroll
        for (int j = 0; j < 8; j++)
            o8[j] = acc[i][j] + bias[wc0 + tx * 8 + j];
        if (rope) {
            #pragma unroll
            for (int p = 0; p < 4; p++) {
                const int d = (wc0 + tx * 8 + 2 * p) & (HD - 1);
                float2 cn = *(const float2*)&g_rope[t * HD + d];
                float e = o8[2 * p], o = o8[2 * p + 1];
                o8[2 * p]     = e * cn.x - o * cn.y;
                o8[2 * p + 1] = e * cn.y + o * cn.x;
            }
        }
        float* cp = &C[(size_t)r * Nout + col0 + tx * 8];
        *(float4*)cp       = make_float4(o8[0], o8[1], o8[2], o8[3]);
        *(float4*)(cp + 4) = make_float4(o8[4], o8[5], o8[6], o8[7]);
    }
}

// ---------------- Flash attention: Q-tile 128, KV-tile 64, 128 threads, 8x8 micro ----
// smem: Qs[64][132] ([d][r]) + PK (Ks[64][68] [d][c], reused as Pt[64][132] [c][r])
//       + Vs[64][68] ([c][d]) = 84992 bytes
#define AT_SMEM ((64 * 132 + 64 * 132 + 64 * 68) * 4)

__global__ void __launch_bounds__(128)
attn_kernel(const float* __restrict__ Qm, const float* __restrict__ KVm,
            float* __restrict__ Om)
{
    extern __shared__ float sm[];
    float* Qs = sm;                  // stride 132
    float* PK = sm + 64 * 132;       // Ks stride 68 / Pt stride 132
    float* Vs = sm + 2 * 64 * 132;   // stride 68

    const int b  = blockIdx.z;
    const int h  = blockIdx.y;
    const int qt = blockIdx.x;
    const int kvh = h >> 2;
    const int tid = threadIdx.x;
    const int tx  = tid & 7;         // col group (8 cols)
    const int ty  = tid >> 3;        // row group (8 rows), 0..15

    // load Q tile transposed, fold 1/sqrt(hd)
    const float* qb = Qm + (size_t)(b * TT + qt * 128) * CC + h * HD;
    #pragma unroll 8
    for (int i = 0; i < 64; i++) {
        int e = tid + i * 128;
        int r = e >> 6, d = e & 63;
        Qs[d * 132 + r] = qb[(size_t)r * CC + d] * 0.125f;
    }

    float m[8], l[8], o[8][8];
    #pragma unroll
    for (int i = 0; i < 8; i++) {
        m[i] = -3.0e38f; l[i] = 0.f;
        #pragma unroll
        for (int j = 0; j < 8; j++) o[i][j] = 0.f;
    }

    const int jend = 2 * qt + 1;
    for (int jt = 0; jt <= jend; jt++) {
        __syncthreads();   // prior PV reads of PK/Vs complete (and Qs ready on jt=0)

        const float* kb = KVm + (size_t)(b * TT + jt * 64) * KVLD + kvh * HD;
        const float* vb = kb + 256;
        #pragma unroll 8
        for (int i = 0; i < 32; i++) {
            int e = tid + i * 128;
            int c = e >> 6, d = e & 63;
            PK[d * 68 + c] = kb[(size_t)c * KVLD + d];
            Vs[c * 68 + d] = vb[(size_t)c * KVLD + d];
        }
        __syncthreads();

        // S = Q K^T
        float s[8][8];
        #pragma unroll
        for (int i = 0; i < 8; i++)
            #pragma unroll
            for (int j = 0; j < 8; j++) s[i][j] = 0.f;
        #pragma unroll 16
        for (int kk = 0; kk < 64; kk++) {
            float a[8], kv[8];
            *(float4*)&a[0]  = *(const float4*)&Qs[kk * 132 + ty * 8];
            *(float4*)&a[4]  = *(const float4*)&Qs[kk * 132 + ty * 8 + 4];
            *(float4*)&kv[0] = *(const float4*)&PK[kk * 68 + tx * 8];
            *(float4*)&kv[4] = *(const float4*)&PK[kk * 68 + tx * 8 + 4];
            #pragma unroll
            for (int i = 0; i < 8; i++)
                #pragma unroll
                for (int j = 0; j < 8; j++)
                    s[i][j] = fmaf(a[i], kv[j], s[i][j]);
        }

        if (jt >= 2 * qt) {   // diagonal region: causal mask
            #pragma unroll
            for (int i = 0; i < 8; i++)
                #pragma unroll
                for (int j = 0; j < 8; j++)
                    if (jt * 64 + tx * 8 + j > qt * 128 + ty * 8 + i)
                        s[i][j] = -3.0e38f;
        }

        __syncthreads();   // Ks reads done -> reuse region as Pt
        float* Pt = PK;

        #pragma unroll
        for (int i = 0; i < 8; i++) {
            float mx = s[i][0];
            #pragma unroll
            for (int j = 1; j < 8; j++) mx = fmaxf(mx, s[i][j]);
            mx = fmaxf(mx, __shfl_xor_sync(0xffffffffu, mx, 1));
            mx = fmaxf(mx, __shfl_xor_sync(0xffffffffu, mx, 2));
            mx = fmaxf(mx, __shfl_xor_sync(0xffffffffu, mx, 4));
            float mnew  = fmaxf(m[i], mx);
            float alpha = __expf(m[i] - mnew);
            float rs = 0.f;
            #pragma unroll
            for (int j = 0; j < 8; j++) {
                float p = __expf(s[i][j] - mnew);
                rs += p;
                Pt[(tx * 8 + j) * 132 + ty * 8 + i] = p;
            }
            rs += __shfl_xor_sync(0xffffffffu, rs, 1);
            rs += __shfl_xor_sync(0xffffffffu, rs, 2);
            rs += __shfl_xor_sync(0xffffffffu, rs, 4);
            l[i] = l[i] * alpha + rs;
            m[i] = mnew;
            #pragma unroll
            for (int j = 0; j < 8; j++) o[i][j] *= alpha;
        }
        __syncthreads();   // Pt fully written

        // O += P @ V
        #pragma unroll 16
        for (int c = 0; c < 64; c++) {
            float a[8], v[8];
            *(float4*)&a[0] = *(const float4*)&Pt[c * 132 + ty * 8];
            *(float4*)&a[4] = *(const float4*)&Pt[c * 132 + ty * 8 + 4];
            *(float4*)&v[0] = *(const float4*)&Vs[c * 68 + tx * 8];
            *(float4*)&v[4] = *(const float4*)&Vs[c * 68 + tx * 8 + 4];
            #pragma unroll
            for (int i = 0; i < 8; i++)
                #pragma unroll
                for (int j = 0; j < 8; j++)
                    o[i][j] = fmaf(a[i], v[j], o[i][j]);
        }
    }

    float* ob = Om + (size_t)(b * TT + qt * 128) * CC + h * HD;
    #pragma unroll
    for (int i = 0; i < 8; i++) {
        float inv = 1.f / l[i];
        float* op = &ob[(size_t)(ty * 8 + i) * CC + tx * 8];
        *(float4*)op       = make_float4(o[i][0] * inv, o[i][1] * inv, o[i][2] * inv, o[i][3] * inv);
        *(float4*)(op + 4) = make_float4(o[i][4] * inv, o[i][5] * inv, o[i][6] * inv, o[i][7] * inv);
    }
}

// ---------------- launch ----------------
extern "C" void kernel_launch(void* const* d_in, const int* in_sizes, int n_in,
                              void* d_out, int out_size)
{
    (void)in_sizes; (void)n_in; (void)out_size;
    const float* x  = (const float*)d_in[0];
    const float* wq = (const float*)d_in[1];
    const float* bq = (const float*)d_in[2];
    const float* wk = (const float*)d_in[3];
    const float* bk = (const float*)d_in[4];
    const float* wv = (const float*)d_in[5];
    const float* bv = (const float*)d_in[6];
    const float* wo = (const float*)d_in[7];
    const float* bo = (const float*)d_in[8];
    float* out = (float*)d_out;

    float *q, *kv, *att;
    cudaGetSymbolAddress((void**)&q,   g_q);
    cudaGetSymbolAddress((void**)&kv,  g_kv);
    cudaGetSymbolAddress((void**)&att, g_att);

    rope_table_kernel<<<TT, 32>>>();

    // Q projection (all cols roped)
    sgemm128<<<dim3(CC / 128, MM / 128), 256>>>(x, wq, bq, wq, bq, q, CC, CC, CC, CC);
    // K|V combined projection (K cols roped)
    sgemm128<<<dim3(KVLD / 128, MM / 128), 256>>>(x, wk, bk, wv, bv, kv, CC, KVLD, 256, 256);

    // attention
    cudaFuncSetAttribute(attn_kernel, cudaFuncAttributeMaxDynamicSharedMemorySize, AT_SMEM);
    attn_kernel<<<dim3(TT / 128, NH, BB), 128, AT_SMEM>>>(q, kv, att);

    // output projection (no rope)
    sgemm128<<<dim3(CC / 128, MM / 128), 256>>>(att, wo, bo, wo, bo, out, CC, CC, CC, 0);
}

// round 3
// speedup vs baseline: 1.0558x; 1.0558x over previous
#include <cuda_runtime.h>
#include <cstddef>

// ---------------- problem constants ----------------
#define BB   2
#define TT   2048
#define CC   1024
#define NH   16
#define HD   64
#define KVLD 512              // combined K|V row stride
#define MM   (BB * TT)        // 4096
#define ROPE_C 0.14391156831212787f   // ln(10000)/64

// ---------------- scratch ----------------
__device__ float g_q  [MM * CC];      // Q (roped)
__device__ float g_kv [MM * KVLD];    // [K(roped) | V]
__device__ float g_att[MM * CC];      // attention output
__device__ float g_rope[TT * HD];     // per (t, even d): cos at [t*64+d], sin at +1

// ---------------- rope table ----------------
__global__ void rope_table_kernel()
{
    int t = blockIdx.x;
    int p = threadIdx.x;                  // 0..31
    float inv = expf(-(float)(2 * p) * ROPE_C);
    float sn, cs;
    sincosf((float)t * inv, &sn, &cs);
    g_rope[t * HD + 2 * p]     = cs;
    g_rope[t * HD + 2 * p + 1] = sn;
}

// ---------------- SGEMM 128x128 tile, 8x8 micro, 256 threads ----------------
__global__ void __launch_bounds__(256, 2)
sgemm128(const float* __restrict__ A,
         const float* __restrict__ W0, const float* __restrict__ b0,
         const float* __restrict__ W1, const float* __restrict__ b1,
         float* __restrict__ C, int K, int Nout, int split, int rope_until)
{
    __shared__ float As[16][132];   // [k][m]
    __shared__ float Bs[16][128];   // [k][n]

    const int tid = threadIdx.x;
    const int tx  = tid & 15;
    const int ty  = tid >> 4;
    const int row0 = blockIdx.y * 128;
    const int col0 = blockIdx.x * 128;

    const float* W; const float* bias; int ldw, wc0;
    if (col0 < split) { W = W0; bias = b0; ldw = split;        wc0 = col0;         }
    else              { W = W1; bias = b1; ldw = Nout - split; wc0 = col0 - split; }

    const int am  = tid >> 1;
    const int akq = (tid & 1) * 8;
    const int bkk = tid >> 4;
    const int bn  = (tid & 15) * 8;

    const float* Aptr = A + (size_t)(row0 + am) * K + akq;
    const float* Wptr = W + (size_t)bkk * ldw + wc0 + bn;

    float acc[8][8];
    #pragma unroll
    for (int i = 0; i < 8; i++)
        #pragma unroll
        for (int j = 0; j < 8; j++) acc[i][j] = 0.f;

    for (int k0 = 0; k0 < K; k0 += 16) {
        float4 a0 = *(const float4*)(Aptr + k0);
        float4 a1 = *(const float4*)(Aptr + k0 + 4);
        float4 w0 = *(const float4*)(Wptr + (size_t)k0 * ldw);
        float4 w1 = *(const float4*)(Wptr + (size_t)k0 * ldw + 4);

        As[akq + 0][am] = a0.x; As[akq + 1][am] = a0.y;
        As[akq + 2][am] = a0.z; As[akq + 3][am] = a0.w;
        As[akq + 4][am] = a1.x; As[akq + 5][am] = a1.y;
        As[akq + 6][am] = a1.z; As[akq + 7][am] = a1.w;
        *(float4*)&Bs[bkk][bn]     = w0;
        *(float4*)&Bs[bkk][bn + 4] = w1;
        __syncthreads();

        #pragma unroll
        for (int kk = 0; kk < 16; kk++) {
            float a[8], b[8];
            *(float4*)&a[0] = *(const float4*)&As[kk][ty * 8];
            *(float4*)&a[4] = *(const float4*)&As[kk][ty * 8 + 4];
            *(float4*)&b[0] = *(const float4*)&Bs[kk][tx * 8];
            *(float4*)&b[4] = *(const float4*)&Bs[kk][tx * 8 + 4];
            #pragma unroll
            for (int i = 0; i < 8; i++)
                #pragma unroll
                for (int j = 0; j < 8; j++)
                    acc[i][j] = fmaf(a[i], b[j], acc[i][j]);
        }
        __syncthreads();
    }

    const bool rope = (col0 < rope_until);
    #pragma unroll
    for (int i = 0; i < 8; i++) {
        const int r = row0 + ty * 8 + i;
        const int t = r & (TT - 1);
        float o8[8];
        #pragma unroll
        for (int j = 0; j < 8; j++)
            o8[j] = acc[i][j] + bias[wc0 + tx * 8 + j];
        if (rope) {
            #pragma unroll
            for (int p = 0; p < 4; p++) {
                const int d = (wc0 + tx * 8 + 2 * p) & (HD - 1);
                float2 cn = *(const float2*)&g_rope[t * HD + d];
                float e = o8[2 * p], o = o8[2 * p + 1];
                o8[2 * p]     = e * cn.x - o * cn.y;
                o8[2 * p + 1] = e * cn.y + o * cn.x;
            }
        }
        float* cp = &C[(size_t)r * Nout + col0 + tx * 8];
        *(float4*)cp       = make_float4(o8[0], o8[1], o8[2], o8[3]);
        *(float4*)(cp + 4) = make_float4(o8[4], o8[5], o8[6], o8[7]);
    }
}

// ---------------- Flash attention ----------------
// 256 threads (8 warps), Q-tile 128, KV-tile 64, micro-tile 8 rows x 4 cols.
// Thread grid: tx = tid&15 (16 x 4 cols = 64), ty = tid>>4 (16 x 8 rows = 128).
// smem: Qs[64][132] + (Ks[64][68] reused as Pt[64][132]) + Vs[64][68] = 84992 B
// -> 2 CTAs/SM (170 KB), 16 warps/SM.
#define AT_SMEM ((64 * 132 + 64 * 132 + 64 * 68) * 4)

__global__ void __launch_bounds__(256, 2)
attn_kernel(const float* __restrict__ Qm, const float* __restrict__ KVm,
            float* __restrict__ Om)
{
    extern __shared__ float sm[];
    float* Qs = sm;                  // stride 132, [d][r]
    float* PK = sm + 64 * 132;       // Ks stride 68 [d][c] / Pt stride 132 [c][r]
    float* Vs = sm + 2 * 64 * 132;   // stride 68, [c][d]

    const int b  = blockIdx.z;
    const int h  = blockIdx.y;
    const int qt = blockIdx.x;
    const int kvh = h >> 2;
    const int tid = threadIdx.x;
    const int tx  = tid & 15;        // 4-col group
    const int ty  = tid >> 4;        // 8-row group

    // load Q tile transposed, fold 1/sqrt(hd)
    const float* qb = Qm + (size_t)(b * TT + qt * 128) * CC + h * HD;
    #pragma unroll 8
    for (int i = 0; i < 32; i++) {
        int e = tid + i * 256;
        int r = e >> 6, d = e & 63;
        Qs[d * 132 + r] = qb[(size_t)r * CC + d] * 0.125f;
    }

    float m[8], l[8], o[8][4];
    #pragma unroll
    for (int i = 0; i < 8; i++) {
        m[i] = -3.0e38f; l[i] = 0.f;
        #pragma unroll
        for (int j = 0; j < 4; j++) o[i][j] = 0.f;
    }

    const int jend = 2 * qt + 1;
    for (int jt = 0; jt <= jend; jt++) {
        __syncthreads();   // prior PV reads of PK/Vs complete (Qs ready on jt=0)

        const float* kb = KVm + (size_t)(b * TT + jt * 64) * KVLD + kvh * HD;
        const float* vb = kb + 256;
        #pragma unroll 8
        for (int i = 0; i < 16; i++) {
            int e = tid + i * 256;
            int c = e >> 6, d = e & 63;
            PK[d * 68 + c] = kb[(size_t)c * KVLD + d];
            Vs[c * 68 + d] = vb[(size_t)c * KVLD + d];
        }
        __syncthreads();

        // S = Q K^T : rows ty*8.., cols tx*4..
        float s[8][4];
        #pragma unroll
        for (int i = 0; i < 8; i++)
            #pragma unroll
            for (int j = 0; j < 4; j++) s[i][j] = 0.f;
        #pragma unroll 16
        for (int kk = 0; kk < 64; kk++) {
            float a[8], kv[4];
            *(float4*)&a[0]  = *(const float4*)&Qs[kk * 132 + ty * 8];
            *(float4*)&a[4]  = *(const float4*)&Qs[kk * 132 + ty * 8 + 4];
            *(float4*)&kv[0] = *(const float4*)&PK[kk * 68 + tx * 4];
            #pragma unroll
            for (int i = 0; i < 8; i++)
                #pragma unroll
                for (int j = 0; j < 4; j++)
                    s[i][j] = fmaf(a[i], kv[j], s[i][j]);
        }

        if (jt >= 2 * qt) {   // diagonal tiles: causal mask
            #pragma unroll
            for (int i = 0; i < 8; i++)
                #pragma unroll
                for (int j = 0; j < 4; j++)
                    if (jt * 64 + tx * 4 + j > qt * 128 + ty * 8 + i)
                        s[i][j] = -3.0e38f;
        }

        __syncthreads();   // Ks reads done -> reuse as Pt
        float* Pt = PK;

        #pragma unroll
        for (int i = 0; i < 8; i++) {
            float mx = fmaxf(fmaxf(s[i][0], s[i][1]), fmaxf(s[i][2], s[i][3]));
            mx = fmaxf(mx, __shfl_xor_sync(0xffffffffu, mx, 1));
            mx = fmaxf(mx, __shfl_xor_sync(0xffffffffu, mx, 2));
            mx = fmaxf(mx, __shfl_xor_sync(0xffffffffu, mx, 4));
            mx = fmaxf(mx, __shfl_xor_sync(0xffffffffu, mx, 8));
            float mnew  = fmaxf(m[i], mx);
            float alpha = __expf(m[i] - mnew);
            float rs = 0.f;
            #pragma unroll
            for (int j = 0; j < 4; j++) {
                float p = __expf(s[i][j] - mnew);
                rs += p;
                Pt[(tx * 4 + j) * 132 + ty * 8 + i] = p;
            }
            rs += __shfl_xor_sync(0xffffffffu, rs, 1);
            rs += __shfl_xor_sync(0xffffffffu, rs, 2);
            rs += __shfl_xor_sync(0xffffffffu, rs, 4);
            rs += __shfl_xor_sync(0xffffffffu, rs, 8);
            l[i] = l[i] * alpha + rs;
            m[i] = mnew;
            #pragma unroll
            for (int j = 0; j < 4; j++) o[i][j] *= alpha;
        }
        __syncthreads();   // Pt fully written

        // O += P @ V : o cols = hd dims tx*4..
        #pragma unroll 16
        for (int c = 0; c < 64; c++) {
            float a[8], v[4];
            *(float4*)&a[0] = *(const float4*)&Pt[c * 132 + ty * 8];
            *(float4*)&a[4] = *(const float4*)&Pt[c * 132 + ty * 8 + 4];
            *(float4*)&v[0] = *(const float4*)&Vs[c * 68 + tx * 4];
            #pragma unroll
            for (int i = 0; i < 8; i++)
                #pragma unroll
                for (int j = 0; j < 4; j++)
                    o[i][j] = fmaf(a[i], v[j], o[i][j]);
        }
    }

    float* ob = Om + (size_t)(b * TT + qt * 128) * CC + h * HD;
    #pragma unroll
    for (int i = 0; i < 8; i++) {
        float inv = 1.f / l[i];
        *(float4*)&ob[(size_t)(ty * 8 + i) * CC + tx * 4] =
            make_float4(o[i][0] * inv, o[i][1] * inv, o[i][2] * inv, o[i][3] * inv);
    }
}

// ---------------- launch ----------------
extern "C" void kernel_launch(void* const* d_in, const int* in_sizes, int n_in,
                              void* d_out, int out_size)
{
    (void)in_sizes; (void)n_in; (void)out_size;
    const float* x  = (const float*)d_in[0];
    const float* wq = (const float*)d_in[1];
    const float* bq = (const float*)d_in[2];
    const float* wk = (const float*)d_in[3];
    const float* bk = (const float*)d_in[4];
    const float* wv = (const float*)d_in[5];
    const float* bv = (const float*)d_in[6];
    const float* wo = (const float*)d_in[7];
    const float* bo = (const float*)d_in[8];
    float* out = (float*)d_out;

    float *q, *kv, *att;
    cudaGetSymbolAddress((void**)&q,   g_q);
    cudaGetSymbolAddress((void**)&kv,  g_kv);
    cudaGetSymbolAddress((void**)&att, g_att);

    rope_table_kernel<<<TT, 32>>>();

    sgemm128<<<dim3(CC / 128, MM / 128), 256>>>(x, wq, bq, wq, bq, q, CC, CC, CC, CC);
    sgemm128<<<dim3(KVLD / 128, MM / 128), 256>>>(x, wk, bk, wv, bv, kv, CC, KVLD, 256, 256);

    cudaFuncSetAttribute(attn_kernel, cudaFuncAttributeMaxDynamicSharedMemorySize, AT_SMEM);
    attn_kernel<<<dim3(TT / 128, NH, BB), 256, AT_SMEM>>>(q, kv, att);

    sgemm128<<<dim3(CC / 128, MM / 128), 256>>>(att, wo, bo, wo, bo, out, CC, CC, CC, 0);
}

// round 6
// speedup vs baseline: 1.2538x; 1.1876x over previous
#include <cuda_runtime.h>
#include <cuda_bf16.h>
#include <cstdint>
#include <cstddef>

// ---------------- problem constants ----------------
#define BB   2
#define TT   2048
#define CC   1024
#define NH   16
#define HD   64
#define KVLD 512
#define MM   (BB * TT)        // 4096
#define KE   3072             // expanded K (hi|hi|lo vs hi|lo|hi)
#define ROPE_C 0.14391156831212787f

// ---------------- scratch ----------------
__device__ float g_q  [MM * CC];
__device__ float g_kv [MM * KVLD];
__device__ float g_att[MM * CC];
__device__ float g_rope[TT * HD];
__device__ float g_bkv[KVLD];
__device__ __nv_bfloat16 g_xe  [(size_t)MM * KE];    // x expanded
__device__ __nv_bfloat16 g_ae  [(size_t)MM * KE];    // att expanded
__device__ __nv_bfloat16 g_weq [(size_t)CC * KE];    // wq^T expanded
__device__ __nv_bfloat16 g_wekv[(size_t)KVLD * KE];  // [wk|wv]^T expanded
__device__ __nv_bfloat16 g_weo [(size_t)CC * KE];    // wo^T expanded

// ---------------- PTX helpers (baseline ISA only; no sm_103a features) -----
__device__ __forceinline__ uint32_t smem_u32(const void* p) {
    uint32_t a;
    asm("{ .reg .u64 t; cvta.to.shared.u64 t, %1; cvt.u32.u64 %0, t; }" : "=r"(a) : "l"(p));
    return a;
}
__device__ __forceinline__ void ldsm_x4(uint32_t* r, uint32_t addr) {
    asm volatile("ldmatrix.sync.aligned.m8n8.x4.shared.b16 {%0,%1,%2,%3}, [%4];"
                 : "=r"(r[0]), "=r"(r[1]), "=r"(r[2]), "=r"(r[3]) : "r"(addr));
}
__device__ __forceinline__ void mma16816(float* d, const uint32_t* a, uint32_t b0, uint32_t b1) {
    asm volatile("mma.sync.aligned.m16n8k16.row.col.f32.bf16.bf16.f32 "
                 "{%0,%1,%2,%3}, {%4,%5,%6,%7}, {%8,%9}, {%0,%1,%2,%3};"
                 : "+f"(d[0]), "+f"(d[1]), "+f"(d[2]), "+f"(d[3])
                 : "r"(a[0]), "r"(a[1]), "r"(a[2]), "r"(a[3]), "r"(b0), "r"(b1));
}

// ---------------- small kernels ----------------
__global__ void rope_table_kernel() {
    int t = blockIdx.x, p = threadIdx.x;
    float inv = expf(-(float)(2 * p) * ROPE_C);
    float sn, cs;
    sincosf((float)t * inv, &sn, &cs);
    g_rope[t * HD + 2 * p]     = cs;
    g_rope[t * HD + 2 * p + 1] = sn;
}

__global__ void pack_bkv_kernel(const float* __restrict__ bk, const float* __restrict__ bv) {
    int i = threadIdx.x;          // 256 threads
    g_bkv[i]       = bk[i];
    g_bkv[256 + i] = bv[i];
}

// A-side split: dst[r][k]=hi, dst[r][1024+k]=hi, dst[r][2048+k]=lo
__global__ void convert_a_kernel(const float* __restrict__ src, __nv_bfloat16* __restrict__ dst) {
    for (int idx = blockIdx.x * blockDim.x + threadIdx.x; idx < MM * CC; idx += gridDim.x * blockDim.x) {
        int r = idx >> 10, k = idx & 1023;
        float v = src[idx];
        __nv_bfloat16 hi = __float2bfloat16(v);
        __nv_bfloat16 lo = __float2bfloat16(v - __bfloat162float(hi));
        size_t b = (size_t)r * KE + k;
        dst[b] = hi; dst[b + 1024] = hi; dst[b + 2048] = lo;
    }
}

// B-side split (transposed): dst[n][k]=hi, [n][1024+k]=lo, [n][2048+k]=hi
__global__ void convert_w_kernel(const float* __restrict__ w, int N,
                                 __nv_bfloat16* __restrict__ dst, int n_off) {
    for (int idx = blockIdx.x * blockDim.x + threadIdx.x; idx < 1024 * N; idx += gridDim.x * blockDim.x) {
        int k = idx / N, n = idx - k * N;
        float v = w[idx];
        __nv_bfloat16 hi = __float2bfloat16(v);
        __nv_bfloat16 lo = __float2bfloat16(v - __bfloat162float(hi));
        size_t b = (size_t)(n_off + n) * KE + k;
        dst[b] = hi; dst[b + 1024] = lo; dst[b + 2048] = hi;
    }
}

// ---------------- HMMA GEMM: C[128x128] = A[M x KE] @ W[N x KE]^T ------------
// 256 threads = 8 warps (2 row x 4 col), warp tile 64x32, BK=64, double buffer.
// smem per buffer: A 128x64 bf16 (16KB, SW-XOR swizzled 128B rows) + B same.
#define GSM_TOTAL (4 * 16384)

__device__ __forceinline__ void stage_tile(char* sA, char* sB,
                                           const __nv_bfloat16* Ap, const __nv_bfloat16* Wp,
                                           int k0, int tid)
{
    #pragma unroll
    for (int i = 0; i < 4; i++) {
        int e   = tid + i * 256;         // 0..1023
        int row = e >> 3, ch = e & 7;
        uint4 va = *(const uint4*)(Ap + (size_t)row * KE + k0 + ch * 8);
        uint4 vb = *(const uint4*)(Wp + (size_t)row * KE + k0 + ch * 8);
        uint32_t sw = row * 128 + ((ch ^ (row & 7)) << 4);
        *(uint4*)(sA + sw) = va;
        *(uint4*)(sB + sw) = vb;
    }
}

__global__ void __launch_bounds__(256, 2)
mma_gemm(const __nv_bfloat16* __restrict__ A, const __nv_bfloat16* __restrict__ W,
         const float* __restrict__ bias, float* __restrict__ C, int ldc, int rope_until)
{
    extern __shared__ char smem[];
    char* bufA[2] = { smem,          smem + 32768 };
    char* bufB[2] = { smem + 16384,  smem + 49152 };
    const uint32_t sb = smem_u32(smem);
    const uint32_t sA32[2] = { sb,          sb + 32768 };
    const uint32_t sB32[2] = { sb + 16384,  sb + 49152 };

    const int tid  = threadIdx.x;
    const int wid  = tid >> 5;
    const int lane = tid & 31;
    const int warpRow = wid & 1;       // 2 blocks of 64 rows
    const int warpCol = wid >> 1;      // 4 blocks of 32 cols
    const int row0 = blockIdx.y * 128;
    const int col0 = blockIdx.x * 128;

    const __nv_bfloat16* Ap = A + (size_t)row0 * KE;
    const __nv_bfloat16* Wp = W + (size_t)col0 * KE;

    // ldmatrix per-lane address components
    const int rx   = lane & 7;                                  // row % 8 (both A and B)
    const int rowA = warpRow * 64 + (lane & 7) + ((lane >> 3) & 1) * 8;
    const int hiA  = (lane >> 4) & 1;                           // k-halves
    const int rowB = warpCol * 32 + (lane & 7) + ((lane >> 4) & 1) * 8;
    const int hiB  = (lane >> 3) & 1;

    float acc[4][4][4];
    #pragma unroll
    for (int mi = 0; mi < 4; mi++)
        #pragma unroll
        for (int nb = 0; nb < 4; nb++)
            #pragma unroll
            for (int q = 0; q < 4; q++) acc[mi][nb][q] = 0.f;

    stage_tile(bufA[0], bufB[0], Ap, Wp, 0, tid);
    __syncthreads();

    const int NIT = KE / 64;   // 48
    for (int it = 0; it < NIT; it++) {
        const int cur = it & 1;
        if (it + 1 < NIT)
            stage_tile(bufA[cur ^ 1], bufB[cur ^ 1], Ap, Wp, (it + 1) * 64, tid);

        const uint32_t aBase = sA32[cur] + rowA * 128;
        const uint32_t bBase = sB32[cur] + rowB * 128;
        #pragma unroll
        for (int kk = 0; kk < 4; kk++) {
            uint32_t a[4][4], b[2][4];
            #pragma unroll
            for (int mi = 0; mi < 4; mi++)
                ldsm_x4(a[mi], aBase + mi * 2048 + ((((kk * 2 + hiA) ^ rx)) << 4));
            #pragma unroll
            for (int nj = 0; nj < 2; nj++)
                ldsm_x4(b[nj], bBase + nj * 2048 + ((((kk * 2 + hiB) ^ rx)) << 4));
            #pragma unroll
            for (int mi = 0; mi < 4; mi++) {
                mma16816(acc[mi][0], a[mi], b[0][0], b[0][1]);
                mma16816(acc[mi][1], a[mi], b[0][2], b[0][3]);
                mma16816(acc[mi][2], a[mi], b[1][0], b[1][1]);
                mma16816(acc[mi][3], a[mi], b[1][2], b[1][3]);
            }
        }
        __syncthreads();
    }

    // epilogue: bias + rope, write fp32
    const int g  = lane >> 2;
    const int tg = lane & 3;
    #pragma unroll
    for (int mi = 0; mi < 4; mi++) {
        #pragma unroll
        for (int nb = 0; nb < 4; nb++) {
            const int col = col0 + warpCol * 32 + nb * 8 + tg * 2;
            const float bx = bias[col], by = bias[col + 1];
            const bool rp  = (col < rope_until);
            #pragma unroll
            for (int half = 0; half < 2; half++) {
                const int r = row0 + warpRow * 64 + mi * 16 + g + half * 8;
                float x = acc[mi][nb][half * 2]     + bx;
                float y = acc[mi][nb][half * 2 + 1] + by;
                if (rp) {
                    const int t = r & (TT - 1);
                    float2 cn = *(const float2*)&g_rope[t * HD + (col & (HD - 1))];
                    float e = x, o = y;
                    x = e * cn.x - o * cn.y;
                    y = e * cn.y + o * cn.x;
                }
                *(float2*)(C + (size_t)r * ldc + col) = make_float2(x, y);
            }
        }
    }
}

// ---------------- Flash attention (R3 version; at fp32 SIMT roofline) --------
#define AT_SMEM ((64 * 132 + 64 * 132 + 64 * 68) * 4)

__global__ void __launch_bounds__(256, 2)
attn_kernel(const float* __restrict__ Qm, const float* __restrict__ KVm,
            float* __restrict__ Om)
{
    extern __shared__ float sm[];
    float* Qs = sm;
    float* PK = sm + 64 * 132;
    float* Vs = sm + 2 * 64 * 132;

    const int b  = blockIdx.z;
    const int h  = blockIdx.y;
    const int qt = blockIdx.x;
    const int kvh = h >> 2;
    const int tid = threadIdx.x;
    const int tx  = tid & 15;
    const int ty  = tid >> 4;

    const float* qb = Qm + (size_t)(b * TT + qt * 128) * CC + h * HD;
    #pragma unroll 8
    for (int i = 0; i < 32; i++) {
        int e = tid + i * 256;
        int r = e >> 6, d = e & 63;
        Qs[d * 132 + r] = qb[(size_t)r * CC + d] * 0.125f;
    }

    float m[8], l[8], o[8][4];
    #pragma unroll
    for (int i = 0; i < 8; i++) {
        m[i] = -3.0e38f; l[i] = 0.f;
        #pragma unroll
        for (int j = 0; j < 4; j++) o[i][j] = 0.f;
    }

    const int jend = 2 * qt + 1;
    for (int jt = 0; jt <= jend; jt++) {
        __syncthreads();
        const float* kb = KVm + (size_t)(b * TT + jt * 64) * KVLD + kvh * HD;
        const float* vb = kb + 256;
        #pragma unroll 8
        for (int i = 0; i < 16; i++) {
            int e = tid + i * 256;
            int c = e >> 6, d = e & 63;
            PK[d * 68 + c] = kb[(size_t)c * KVLD + d];
            Vs[c * 68 + d] = vb[(size_t)c * KVLD + d];
        }
        __syncthreads();

        float s[8][4];
        #pragma unroll
        for (int i = 0; i < 8; i++)
            #pragma unroll
            for (int j = 0; j < 4; j++) s[i][j] = 0.f;
        #pragma unroll 16
        for (int kk = 0; kk < 64; kk++) {
            float a[8], kv[4];
            *(float4*)&a[0]  = *(const float4*)&Qs[kk * 132 + ty * 8];
            *(float4*)&a[4]  = *(const float4*)&Qs[kk * 132 + ty * 8 + 4];
            *(float4*)&kv[0] = *(const float4*)&PK[kk * 68 + tx * 4];
            #pragma unroll
            for (int i = 0; i < 8; i++)
                #pragma unroll
                for (int j = 0; j < 4; j++)
                    s[i][j] = fmaf(a[i], kv[j], s[i][j]);
        }

        if (jt >= 2 * qt) {
            #pragma unroll
            for (int i = 0; i < 8; i++)
                #pragma unroll
                for (int j = 0; j < 4; j++)
                    if (jt * 64 + tx * 4 + j > qt * 128 + ty * 8 + i)
                        s[i][j] = -3.0e38f;
        }

        __syncthreads();
        float* Pt = PK;

        #pragma unroll
        for (int i = 0; i < 8; i++) {
            float mx = fmaxf(fmaxf(s[i][0], s[i][1]), fmaxf(s[i][2], s[i][3]));
            mx = fmaxf(mx, __shfl_xor_sync(0xffffffffu, mx, 1));
            mx = fmaxf(mx, __shfl_xor_sync(0xffffffffu, mx, 2));
            mx = fmaxf(mx, __shfl_xor_sync(0xffffffffu, mx, 4));
            mx = fmaxf(mx, __shfl_xor_sync(0xffffffffu, mx, 8));
            float mnew  = fmaxf(m[i], mx);
            float alpha = __expf(m[i] - mnew);
            float rs = 0.f;
            #pragma unroll
            for (int j = 0; j < 4; j++) {
                float p = __expf(s[i][j] - mnew);
                rs += p;
                Pt[(tx * 4 + j) * 132 + ty * 8 + i] = p;
            }
            rs += __shfl_xor_sync(0xffffffffu, rs, 1);
            rs += __shfl_xor_sync(0xffffffffu, rs, 2);
            rs += __shfl_xor_sync(0xffffffffu, rs, 4);
            rs += __shfl_xor_sync(0xffffffffu, rs, 8);
            l[i] = l[i] * alpha + rs;
            m[i] = mnew;
            #pragma unroll
            for (int j = 0; j < 4; j++) o[i][j] *= alpha;
        }
        __syncthreads();

        #pragma unroll 16
        for (int c = 0; c < 64; c++) {
            float a[8], v[4];
            *(float4*)&a[0] = *(const float4*)&Pt[c * 132 + ty * 8];
            *(float4*)&a[4] = *(const float4*)&Pt[c * 132 + ty * 8 + 4];
            *(float4*)&v[0] = *(const float4*)&Vs[c * 68 + tx * 4];
            #pragma unroll
            for (int i = 0; i < 8; i++)
                #pragma unroll
                for (int j = 0; j < 4; j++)
                    o[i][j] = fmaf(a[i], v[j], o[i][j]);
        }
    }

    float* ob = Om + (size_t)(b * TT + qt * 128) * CC + h * HD;
    #pragma unroll
    for (int i = 0; i < 8; i++) {
        float inv = 1.f / l[i];
        *(float4*)&ob[(size_t)(ty * 8 + i) * CC + tx * 4] =
            make_float4(o[i][0] * inv, o[i][1] * inv, o[i][2] * inv, o[i][3] * inv);
    }
}

// ---------------- launch ----------------
extern "C" void kernel_launch(void* const* d_in, const int* in_sizes, int n_in,
                              void* d_out, int out_size)
{
    (void)in_sizes; (void)n_in; (void)out_size;
    const float* x  = (const float*)d_in[0];
    const float* wq = (const float*)d_in[1];
    const float* bq = (const float*)d_in[2];
    const float* wk = (const float*)d_in[3];
    const float* bk = (const float*)d_in[4];
    const float* wv = (const float*)d_in[5];
    const float* bv = (const float*)d_in[6];
    const float* wo = (const float*)d_in[7];
    const float* bo = (const float*)d_in[8];
    float* out = (float*)d_out;

    float *q, *kv, *att, *bkv;
    __nv_bfloat16 *xe, *ae, *weq, *wekv, *weo;
    cudaGetSymbolAddress((void**)&q,    g_q);
    cudaGetSymbolAddress((void**)&kv,   g_kv);
    cudaGetSymbolAddress((void**)&att,  g_att);
    cudaGetSymbolAddress((void**)&bkv,  g_bkv);
    cudaGetSymbolAddress((void**)&xe,   g_xe);
    cudaGetSymbolAddress((void**)&ae,   g_ae);
    cudaGetSymbolAddress((void**)&weq,  g_weq);
    cudaGetSymbolAddress((void**)&wekv, g_wekv);
    cudaGetSymbolAddress((void**)&weo,  g_weo);

    cudaFuncSetAttribute(mma_gemm,    cudaFuncAttributeMaxDynamicSharedMemorySize, GSM_TOTAL);
    cudaFuncSetAttribute(attn_kernel, cudaFuncAttributeMaxDynamicSharedMemorySize, AT_SMEM);

    rope_table_kernel<<<TT, 32>>>();
    pack_bkv_kernel<<<1, 256>>>(bk, bv);
    convert_a_kernel<<<2048, 256>>>(x, xe);
    convert_w_kernel<<<1024, 256>>>(wq, 1024, weq, 0);
    convert_w_kernel<<<512, 256>>>(wk, 256, wekv, 0);
    convert_w_kernel<<<512, 256>>>(wv, 256, wekv, 256);
    convert_w_kernel<<<1024, 256>>>(wo, 1024, weo, 0);

    // Q projection: N=1024, rope all cols
    mma_gemm<<<dim3(CC / 128, MM / 128), 256, GSM_TOTAL>>>(xe, weq, bq, q, CC, CC);
    // K|V projection: N=512, rope cols < 256
    mma_gemm<<<dim3(KVLD / 128, MM / 128), 256, GSM_TOTAL>>>(xe, wekv, bkv, kv, KVLD, 256);

    attn_kernel<<<dim3(TT / 128, NH, BB), 256, AT_SMEM>>>(q, kv, att);

    convert_a_kernel<<<2048, 256>>>(att, ae);
    // O projection: no rope
    mma_gemm<<<dim3(CC / 128, MM / 128), 256, GSM_TOTAL>>>(ae, weo, bo, out, CC, 0);
}

// round 7
// speedup vs baseline: 2.0675x; 1.6489x over previous
#include <cuda_runtime.h>
#include <cuda_bf16.h>
#include <cstdint>
#include <cstddef>

// ---------------- problem constants ----------------
#define BB   2
#define TT   2048
#define CC   1024
#define NH   16
#define HD   64
#define MM   (BB * TT)        // 4096
#define KE   3072             // expanded K for projections (hi|hi|lo vs hi|lo|hi)
#define ROPE_C 0.14391156831212787f

// ---------------- scratch ----------------
__device__ float g_rope[TT * HD];
__device__ float g_bkv[512];
__device__ __nv_bfloat16 g_xe  [(size_t)MM * KE];     // x expanded (A-side)
__device__ __nv_bfloat16 g_ae  [(size_t)MM * KE];     // attn out expanded (A-side)
__device__ __nv_bfloat16 g_weq [(size_t)CC * KE];     // wq^T expanded (B-side)
__device__ __nv_bfloat16 g_wekv[(size_t)512 * KE];    // [wk|wv]^T expanded
__device__ __nv_bfloat16 g_weo [(size_t)CC * KE];     // wo^T expanded
__device__ __nv_bfloat16 g_qe  [(size_t)MM * NH * 128];   // Q: [r][h][hi(64)|lo(64)], scaled
__device__ __nv_bfloat16 g_kve [(size_t)MM * 4 * 128];    // K: [r][kvh][hi|lo]
__device__ __nv_bfloat16 g_vt  [(size_t)BB * 4 * 128 * TT]; // V^T: [b][kvh][hi d|lo d][t]

// ---------------- PTX helpers (baseline ISA only) ----------------
__device__ __forceinline__ uint32_t smem_u32(const void* p) {
    uint32_t a;
    asm("{ .reg .u64 t; cvta.to.shared.u64 t, %1; cvt.u32.u64 %0, t; }" : "=r"(a) : "l"(p));
    return a;
}
__device__ __forceinline__ void ldsm_x4(uint32_t* r, uint32_t addr) {
    asm volatile("ldmatrix.sync.aligned.m8n8.x4.shared.b16 {%0,%1,%2,%3}, [%4];"
                 : "=r"(r[0]), "=r"(r[1]), "=r"(r[2]), "=r"(r[3]) : "r"(addr));
}
__device__ __forceinline__ void mma16816(float* d, const uint32_t* a, uint32_t b0, uint32_t b1) {
    asm volatile("mma.sync.aligned.m16n8k16.row.col.f32.bf16.bf16.f32 "
                 "{%0,%1,%2,%3}, {%4,%5,%6,%7}, {%8,%9}, {%0,%1,%2,%3};"
                 : "+f"(d[0]), "+f"(d[1]), "+f"(d[2]), "+f"(d[3])
                 : "r"(a[0]), "r"(a[1]), "r"(a[2]), "r"(a[3]), "r"(b0), "r"(b1));
}
__device__ __forceinline__ void cp16(uint32_t dst, const void* src) {
    asm volatile("cp.async.cg.shared.global [%0], [%1], 16;" :: "r"(dst), "l"(src));
}
#define CP_COMMIT() asm volatile("cp.async.commit_group;" ::: "memory")
#define CP_WAIT1()  asm volatile("cp.async.wait_group 1;" ::: "memory")
#define CP_WAIT0()  asm volatile("cp.async.wait_group 0;" ::: "memory")

__device__ __forceinline__ uint32_t pack_bf2(__nv_bfloat16 x, __nv_bfloat16 y) {
    union { __nv_bfloat162 h; uint32_t u; } c;
    c.h = __nv_bfloat162(x, y);
    return c.u;
}

// ---------------- small kernels ----------------
__global__ void rope_table_kernel() {
    int t = blockIdx.x, p = threadIdx.x;
    float inv = expf(-(float)(2 * p) * ROPE_C);
    float sn, cs;
    sincosf((float)t * inv, &sn, &cs);
    g_rope[t * HD + 2 * p]     = cs;
    g_rope[t * HD + 2 * p + 1] = sn;
}
__global__ void pack_bkv_kernel(const float* __restrict__ bk, const float* __restrict__ bv) {
    int i = threadIdx.x;
    g_bkv[i] = bk[i];
    g_bkv[256 + i] = bv[i];
}
__global__ void convert_a_kernel(const float* __restrict__ src, __nv_bfloat16* __restrict__ dst) {
    for (int idx = blockIdx.x * blockDim.x + threadIdx.x; idx < MM * CC; idx += gridDim.x * blockDim.x) {
        int r = idx >> 10, k = idx & 1023;
        float v = src[idx];
        __nv_bfloat16 hi = __float2bfloat16(v);
        __nv_bfloat16 lo = __float2bfloat16(v - __bfloat162float(hi));
        size_t b = (size_t)r * KE + k;
        dst[b] = hi; dst[b + 1024] = hi; dst[b + 2048] = lo;
    }
}
__global__ void convert_w_kernel(const float* __restrict__ w, int N,
                                 __nv_bfloat16* __restrict__ dst, int n_off) {
    for (int idx = blockIdx.x * blockDim.x + threadIdx.x; idx < 1024 * N; idx += gridDim.x * blockDim.x) {
        int k = idx / N, n = idx - k * N;
        float v = w[idx];
        __nv_bfloat16 hi = __float2bfloat16(v);
        __nv_bfloat16 lo = __float2bfloat16(v - __bfloat162float(hi));
        size_t b = (size_t)(n_off + n) * KE + k;
        dst[b] = hi; dst[b + 1024] = lo; dst[b + 2048] = hi;
    }
}

// ---------------- HMMA GEMM: 128x128 tile, 8 warps, BK=64, double buffer -----
// mode 0: Q proj  -> g_qe (rope all, *0.125)
// mode 1: KV proj -> g_kve (K, rope) / g_vt (V transposed)
// mode 2: O proj  -> fp32 C (bias only)
#define GSM_TOTAL (4 * 16384)

__device__ __forceinline__ void stage_tile(char* sA, char* sB,
                                           const __nv_bfloat16* Ap, const __nv_bfloat16* Wp,
                                           int k0, int tid)
{
    #pragma unroll
    for (int i = 0; i < 4; i++) {
        int e   = tid + i * 256;
        int row = e >> 3, ch = e & 7;
        uint4 va = *(const uint4*)(Ap + (size_t)row * KE + k0 + ch * 8);
        uint4 vb = *(const uint4*)(Wp + (size_t)row * KE + k0 + ch * 8);
        uint32_t sw = row * 128 + ((ch ^ (row & 7)) << 4);
        *(uint4*)(sA + sw) = va;
        *(uint4*)(sB + sw) = vb;
    }
}

__global__ void __launch_bounds__(256, 2)
mma_gemm(const __nv_bfloat16* __restrict__ A, const __nv_bfloat16* __restrict__ W,
         const float* __restrict__ bias, float* __restrict__ C, int ldc,
         int rope_until, int mode)
{
    extern __shared__ char smem[];
    char* bufA[2] = { smem,          smem + 32768 };
    char* bufB[2] = { smem + 16384,  smem + 49152 };
    const uint32_t sb = smem_u32(smem);
    const uint32_t sA32[2] = { sb,          sb + 32768 };
    const uint32_t sB32[2] = { sb + 16384,  sb + 49152 };

    const int tid  = threadIdx.x;
    const int wid  = tid >> 5;
    const int lane = tid & 31;
    const int warpRow = wid & 1;
    const int warpCol = wid >> 1;
    const int row0 = blockIdx.y * 128;
    const int col0 = blockIdx.x * 128;

    const __nv_bfloat16* Ap = A + (size_t)row0 * KE;
    const __nv_bfloat16* Wp = W + (size_t)col0 * KE;

    const int rx   = lane & 7;
    const int rowA = warpRow * 64 + (lane & 7) + ((lane >> 3) & 1) * 8;
    const int hiA  = (lane >> 4) & 1;
    const int rowB = warpCol * 32 + (lane & 7) + ((lane >> 4) & 1) * 8;
    const int hiB  = (lane >> 3) & 1;

    float acc[4][4][4];
    #pragma unroll
    for (int mi = 0; mi < 4; mi++)
        #pragma unroll
        for (int nb = 0; nb < 4; nb++)
            #pragma unroll
            for (int q = 0; q < 4; q++) acc[mi][nb][q] = 0.f;

    stage_tile(bufA[0], bufB[0], Ap, Wp, 0, tid);
    __syncthreads();

    const int NIT = KE / 64;
    for (int it = 0; it < NIT; it++) {
        const int cur = it & 1;
        if (it + 1 < NIT)
            stage_tile(bufA[cur ^ 1], bufB[cur ^ 1], Ap, Wp, (it + 1) * 64, tid);

        const uint32_t aBase = sA32[cur] + rowA * 128;
        const uint32_t bBase = sB32[cur] + rowB * 128;
        #pragma unroll
        for (int kk = 0; kk < 4; kk++) {
            uint32_t a[4][4], b[2][4];
            #pragma unroll
            for (int mi = 0; mi < 4; mi++)
                ldsm_x4(a[mi], aBase + mi * 2048 + ((((kk * 2 + hiA) ^ rx)) << 4));
            #pragma unroll
            for (int nj = 0; nj < 2; nj++)
                ldsm_x4(b[nj], bBase + nj * 2048 + ((((kk * 2 + hiB) ^ rx)) << 4));
            #pragma unroll
            for (int mi = 0; mi < 4; mi++) {
                mma16816(acc[mi][0], a[mi], b[0][0], b[0][1]);
                mma16816(acc[mi][1], a[mi], b[0][2], b[0][3]);
                mma16816(acc[mi][2], a[mi], b[1][0], b[1][1]);
                mma16816(acc[mi][3], a[mi], b[1][2], b[1][3]);
            }
        }
        __syncthreads();
    }

    const int g  = lane >> 2;
    const int tg = lane & 3;
    #pragma unroll
    for (int mi = 0; mi < 4; mi++) {
        #pragma unroll
        for (int nb = 0; nb < 4; nb++) {
            const int col = col0 + warpCol * 32 + nb * 8 + tg * 2;
            const float bx = bias[col], by = bias[col + 1];
            const bool rp  = (col < rope_until);
            #pragma unroll
            for (int half = 0; half < 2; half++) {
                const int r = row0 + warpRow * 64 + mi * 16 + g + half * 8;
                float x = acc[mi][nb][half * 2]     + bx;
                float y = acc[mi][nb][half * 2 + 1] + by;
                if (rp) {
                    const int t = r & (TT - 1);
                    float2 cn = *(const float2*)&g_rope[t * HD + (col & (HD - 1))];
                    float e = x, o = y;
                    x = e * cn.x - o * cn.y;
                    y = e * cn.y + o * cn.x;
                }
                if (mode == 2) {
                    *(float2*)(C + (size_t)r * ldc + col) = make_float2(x, y);
                } else if (mode == 0) {
                    x *= 0.125f; y *= 0.125f;
                    __nv_bfloat16 hx = __float2bfloat16(x), hy = __float2bfloat16(y);
                    __nv_bfloat16 lx = __float2bfloat16(x - __bfloat162float(hx));
                    __nv_bfloat16 ly = __float2bfloat16(y - __bfloat162float(hy));
                    const int h = col >> 6, d = col & 63;
                    uint32_t* p = (uint32_t*)&g_qe[((size_t)r * NH + h) * 128 + d];
                    p[0]  = pack_bf2(hx, hy);
                    p[32] = pack_bf2(lx, ly);            // +64 bf16
                } else {
                    __nv_bfloat16 hx = __float2bfloat16(x), hy = __float2bfloat16(y);
                    __nv_bfloat16 lx = __float2bfloat16(x - __bfloat162float(hx));
                    __nv_bfloat16 ly = __float2bfloat16(y - __bfloat162float(hy));
                    if (col < 256) {
                        const int h = col >> 6, d = col & 63;
                        uint32_t* p = (uint32_t*)&g_kve[((size_t)r * 4 + h) * 128 + d];
                        p[0]  = pack_bf2(hx, hy);
                        p[32] = pack_bf2(lx, ly);
                    } else {
                        const int cv = col - 256, h = cv >> 6, d = cv & 63;
                        const int bb = r >> 11, t = r & (TT - 1);
                        __nv_bfloat16* p = &g_vt[(((size_t)(bb * 4 + h) * 128) + d) * TT + t];
                        p[0]        = hx;   // vhi[d][t]
                        p[TT]       = hy;   // vhi[d+1][t]
                        p[64 * TT]  = lx;   // vlo[d][t]
                        p[65 * TT]  = ly;
                    }
                }
            }
        }
    }
}

// ---------------- tensor-core flash attention -------------------------------
// 256 thr = 8 warps, each warp: 16 q-rows. Q-tile 128, KV-chunk 64.
// smem: Qs 128x256B (hi|lo, swz) + K[2] 64x256B + Vt[2] 128x128B = 96KB.
#define AT_QS   0
#define AT_K0   32768
#define AT_V0   65536
#define AT_TOTAL 98304

__device__ __forceinline__ void load_kv_chunk(uint32_t sb, int buf, int b, int kvh,
                                              int t0, int tid)
{
    const __nv_bfloat16* kg = &g_kve[((size_t)(b * TT + t0) * 4 + kvh) * 128];
    const uint32_t kdst = sb + AT_K0 + buf * 16384;
    #pragma unroll
    for (int i = 0; i < 4; i++) {
        int e = tid + i * 256, c = e >> 4, ch = e & 15;
        cp16(kdst + c * 256 + (((ch & 8) | ((ch ^ c) & 7)) << 4), kg + (size_t)c * 512 + ch * 8);
    }
    const __nv_bfloat16* vg = &g_vt[(size_t)(b * 4 + kvh) * 128 * TT + t0];
    const uint32_t vdst = sb + AT_V0 + buf * 16384;
    #pragma unroll
    for (int i = 0; i < 4; i++) {
        int e = tid + i * 256, d = e >> 3, ch = e & 7;
        cp16(vdst + d * 128 + (((ch ^ d) & 7) << 4), vg + (size_t)d * TT + ch * 8);
    }
}

__global__ void __launch_bounds__(256, 2)
attn_kernel()
{
    extern __shared__ char smem[];
    const uint32_t sb = smem_u32(smem);

    const int b  = blockIdx.z;
    const int h  = blockIdx.y;
    const int qt = blockIdx.x;
    const int kvh = h >> 2;
    const int tid  = threadIdx.x;
    const int w    = tid >> 5;
    const int lane = tid & 31;
    const int g    = lane >> 2;
    const int tg   = lane & 3;

    // load Q tile (once)
    {
        const __nv_bfloat16* qg = &g_qe[((size_t)(b * TT + qt * 128) * NH + h) * 128];
        #pragma unroll
        for (int i = 0; i < 8; i++) {
            int e = tid + i * 256, r = e >> 4, ch = e & 15;
            cp16(sb + AT_QS + r * 256 + (((ch & 8) | ((ch ^ r) & 7)) << 4),
                 qg + (size_t)r * (NH * 128) + ch * 8);
        }
    }
    CP_COMMIT();
    load_kv_chunk(sb, 0, b, kvh, 0, tid);
    CP_COMMIT();

    // ldmatrix lane addressing
    const int qrow = w * 16 + (lane & 7) + ((lane >> 3) & 1) * 8;
    const int hiA  = (lane >> 4) & 1;
    const int brow = (lane & 7) + ((lane >> 4) & 1) * 8;   // row within 16-block
    const int hiB  = (lane >> 3) & 1;
    const uint32_t aBase = sb + AT_QS + qrow * 256;

    float m0 = -3.0e38f, m1 = -3.0e38f, l0 = 0.f, l1 = 0.f;
    float ov[8][4];
    #pragma unroll
    for (int nt = 0; nt < 8; nt++)
        #pragma unroll
        for (int q = 0; q < 4; q++) ov[nt][q] = 0.f;

    const int jend = 2 * qt + 1;
    for (int jt = 0; jt <= jend; jt++) {
        if (jt < jend) { load_kv_chunk(sb, (jt + 1) & 1, b, kvh, (jt + 1) * 64, tid); CP_COMMIT(); CP_WAIT1(); }
        else CP_WAIT0();
        __syncthreads();

        const int buf = jt & 1;
        const uint32_t kBase = sb + AT_K0 + buf * 16384;
        const uint32_t vBase = sb + AT_V0 + buf * 16384;

        // ---- S = Qe @ Ke^T (3-pass split) ----
        float sv[8][4];
        #pragma unroll
        for (int nt = 0; nt < 8; nt++)
            #pragma unroll
            for (int q = 0; q < 4; q++) sv[nt][q] = 0.f;

        #pragma unroll
        for (int pass = 0; pass < 3; pass++) {
            const int qo = (pass == 2) ? 8 : 0;
            const int ko = (pass == 1) ? 8 : 0;
            #pragma unroll
            for (int kc = 0; kc < 4; kc++) {
                uint32_t a[4];
                const int chA = qo + 2 * kc + hiA;
                ldsm_x4(a, aBase + (((chA & 8) | ((chA ^ qrow) & 7)) << 4));
                #pragma unroll
                for (int nt2 = 0; nt2 < 4; nt2++) {
                    uint32_t bf[4];
                    const int c = nt2 * 16 + brow;
                    const int chB = ko + 2 * kc + hiB;
                    ldsm_x4(bf, kBase + c * 256 + (((chB & 8) | ((chB ^ c) & 7)) << 4));
                    mma16816(sv[nt2 * 2],     a, bf[0], bf[1]);
                    mma16816(sv[nt2 * 2 + 1], a, bf[2], bf[3]);
                }
            }
        }

        // ---- causal mask (only near diagonal) ----
        const int kc0 = jt * 64;
        if (kc0 + 63 > qt * 128 + w * 16) {
            #pragma unroll
            for (int nt = 0; nt < 8; nt++)
                #pragma unroll
                for (int q = 0; q < 4; q++) {
                    const int row = qt * 128 + w * 16 + g + 8 * (q >> 1);
                    const int col = kc0 + nt * 8 + tg * 2 + (q & 1);
                    if (col > row) sv[nt][q] = -1.0e30f;
                }
        }

        // ---- online softmax (rows g, g+8; quad shuffles over tg) ----
        float mx0 = -3.0e38f, mx1 = -3.0e38f;
        #pragma unroll
        for (int nt = 0; nt < 8; nt++) {
            mx0 = fmaxf(mx0, fmaxf(sv[nt][0], sv[nt][1]));
            mx1 = fmaxf(mx1, fmaxf(sv[nt][2], sv[nt][3]));
        }
        mx0 = fmaxf(mx0, __shfl_xor_sync(0xffffffffu, mx0, 1));
        mx0 = fmaxf(mx0, __shfl_xor_sync(0xffffffffu, mx0, 2));
        mx1 = fmaxf(mx1, __shfl_xor_sync(0xffffffffu, mx1, 1));
        mx1 = fmaxf(mx1, __shfl_xor_sync(0xffffffffu, mx1, 2));
        const float mn0 = fmaxf(m0, mx0), mn1 = fmaxf(m1, mx1);
        const float al0 = __expf(m0 - mn0), al1 = __expf(m1 - mn1);
        float rs0 = 0.f, rs1 = 0.f;
        #pragma unroll
        for (int nt = 0; nt < 8; nt++) {
            sv[nt][0] = __expf(sv[nt][0] - mn0); rs0 += sv[nt][0];
            sv[nt][1] = __expf(sv[nt][1] - mn0); rs0 += sv[nt][1];
            sv[nt][2] = __expf(sv[nt][2] - mn1); rs1 += sv[nt][2];
            sv[nt][3] = __expf(sv[nt][3] - mn1); rs1 += sv[nt][3];
        }
        rs0 += __shfl_xor_sync(0xffffffffu, rs0, 1);
        rs0 += __shfl_xor_sync(0xffffffffu, rs0, 2);
        rs1 += __shfl_xor_sync(0xffffffffu, rs1, 1);
        rs1 += __shfl_xor_sync(0xffffffffu, rs1, 2);
        l0 = l0 * al0 + rs0; l1 = l1 * al1 + rs1;
        m0 = mn0; m1 = mn1;
        #pragma unroll
        for (int nt = 0; nt < 8; nt++) {
            ov[nt][0] *= al0; ov[nt][1] *= al0;
            ov[nt][2] *= al1; ov[nt][3] *= al1;
        }

        // ---- P hi-fragments (C-frag layout == A-frag layout) ----
        uint32_t aph[4][4];
        #pragma unroll
        for (int cc = 0; cc < 4; cc++) {
            aph[cc][0] = pack_bf2(__float2bfloat16(sv[2*cc][0]),   __float2bfloat16(sv[2*cc][1]));
            aph[cc][1] = pack_bf2(__float2bfloat16(sv[2*cc][2]),   __float2bfloat16(sv[2*cc][3]));
            aph[cc][2] = pack_bf2(__float2bfloat16(sv[2*cc+1][0]), __float2bfloat16(sv[2*cc+1][1]));
            aph[cc][3] = pack_bf2(__float2bfloat16(sv[2*cc+1][2]), __float2bfloat16(sv[2*cc+1][3]));
        }

        // ---- O += P @ V (3-pass split: Phi*Vhi, Phi*Vlo, Plo*Vhi) ----
        #pragma unroll
        for (int pass = 0; pass < 3; pass++) {
            const int vro = (pass == 1) ? 64 : 0;
            #pragma unroll
            for (int cc = 0; cc < 4; cc++) {
                uint32_t a[4];
                if (pass < 2) {
                    a[0] = aph[cc][0]; a[1] = aph[cc][1]; a[2] = aph[cc][2]; a[3] = aph[cc][3];
                } else {
                    #pragma unroll
                    for (int q2 = 0; q2 < 2; q2++) {
                        float p0 = sv[2*cc][q2*2],   p1 = sv[2*cc][q2*2+1];
                        float p2 = sv[2*cc+1][q2*2], p3 = sv[2*cc+1][q2*2+1];
                        __nv_bfloat16 h0 = __float2bfloat16(p0), h1 = __float2bfloat16(p1);
                        __nv_bfloat16 h2 = __float2bfloat16(p2), h3 = __float2bfloat16(p3);
                        a[q2]     = pack_bf2(__float2bfloat16(p0 - __bfloat162float(h0)),
                                             __float2bfloat16(p1 - __bfloat162float(h1)));
                        a[q2 + 2] = pack_bf2(__float2bfloat16(p2 - __bfloat162float(h2)),
                                             __float2bfloat16(p3 - __bfloat162float(h3)));
                    }
                }
                #pragma unroll
                for (int nt2 = 0; nt2 < 4; nt2++) {
                    uint32_t bf[4];
                    const int d = vro + nt2 * 16 + brow;
                    const int chV = 2 * cc + hiB;
                    ldsm_x4(bf, vBase + d * 128 + (((chV ^ d) & 7) << 4));
                    mma16816(ov[nt2 * 2],     a, bf[0], bf[1]);
                    mma16816(ov[nt2 * 2 + 1], a, bf[2], bf[3]);
                }
            }
        }
        __syncthreads();
    }

    // ---- epilogue: normalize, write expanded A-layout for O-proj ----
    const float i0 = 1.f / l0, i1 = 1.f / l1;
    const size_t r0g = (size_t)(b * TT + qt * 128 + w * 16 + g);
    #pragma unroll
    for (int nt = 0; nt < 8; nt++) {
        const int dg = h * 64 + nt * 8 + tg * 2;
        #pragma unroll
        for (int half = 0; half < 2; half++) {
            const float x = ov[nt][half * 2]     * (half ? i1 : i0);
            const float y = ov[nt][half * 2 + 1] * (half ? i1 : i0);
            __nv_bfloat16 hx = __float2bfloat16(x), hy = __float2bfloat16(y);
            __nv_bfloat16 lx = __float2bfloat16(x - __bfloat162float(hx));
            __nv_bfloat16 ly = __float2bfloat16(y - __bfloat162float(hy));
            uint32_t* p = (uint32_t*)&g_ae[(r0g + half * 8) * KE + dg];
            p[0]    = pack_bf2(hx, hy);
            p[512]  = pack_bf2(hx, hy);     // +1024 bf16
            p[1024] = pack_bf2(lx, ly);     // +2048 bf16
        }
    }
}

// ---------------- launch ----------------
extern "C" void kernel_launch(void* const* d_in, const int* in_sizes, int n_in,
                              void* d_out, int out_size)
{
    (void)in_sizes; (void)n_in; (void)out_size;
    const float* x  = (const float*)d_in[0];
    const float* wq = (const float*)d_in[1];
    const float* bq = (const float*)d_in[2];
    const float* wk = (const float*)d_in[3];
    const float* bk = (const float*)d_in[4];
    const float* wv = (const float*)d_in[5];
    const float* bv = (const float*)d_in[6];
    const float* wo = (const float*)d_in[7];
    const float* bo = (const float*)d_in[8];
    float* out = (float*)d_out;

    float* bkv;
    __nv_bfloat16 *xe, *ae, *weq, *wekv, *weo;
    cudaGetSymbolAddress((void**)&bkv,  g_bkv);
    cudaGetSymbolAddress((void**)&xe,   g_xe);
    cudaGetSymbolAddress((void**)&ae,   g_ae);
    cudaGetSymbolAddress((void**)&weq,  g_weq);
    cudaGetSymbolAddress((void**)&wekv, g_wekv);
    cudaGetSymbolAddress((void**)&weo,  g_weo);

    cudaFuncSetAttribute(mma_gemm,    cudaFuncAttributeMaxDynamicSharedMemorySize, GSM_TOTAL);
    cudaFuncSetAttribute(attn_kernel, cudaFuncAttributeMaxDynamicSharedMemorySize, AT_TOTAL);

    rope_table_kernel<<<TT, 32>>>();
    pack_bkv_kernel<<<1, 256>>>(bk, bv);
    convert_a_kernel<<<2048, 256>>>(x, xe);
    convert_w_kernel<<<1024, 256>>>(wq, 1024, weq, 0);
    convert_w_kernel<<<512, 256>>>(wk, 256, wekv, 0);
    convert_w_kernel<<<512, 256>>>(wv, 256, wekv, 256);
    convert_w_kernel<<<1024, 256>>>(wo, 1024, weo, 0);

    // Q proj -> g_qe (mode 0); K|V proj -> g_kve/g_vt (mode 1)
    mma_gemm<<<dim3(8, 32), 256, GSM_TOTAL>>>(xe, weq, bq, nullptr, 0, CC, 0);
    mma_gemm<<<dim3(4, 32), 256, GSM_TOTAL>>>(xe, wekv, bkv, nullptr, 0, 256, 1);

    attn_kernel<<<dim3(TT / 128, NH, BB), 256, AT_TOTAL>>>();

    // O proj -> fp32 out (mode 2)
    mma_gemm<<<dim3(8, 32), 256, GSM_TOTAL>>>(ae, weo, bo, out, CC, 0, 2);
}

// round 8
// speedup vs baseline: 2.2962x; 1.1106x over previous
#include <cuda_runtime.h>
#include <cuda_bf16.h>
#include <cstdint>
#include <cstddef>

// ---------------- problem constants ----------------
#define BB   2
#define TT   2048
#define CC   1024
#define NH   16
#define HD   64
#define MM   (BB * TT)        // 4096
#define KE   2048             // [hi(1024) | lo(1024)] operand layout
#define ROPE_C 0.14391156831212787f

// ---------------- scratch ----------------
__device__ float g_rope[TT * HD];
__device__ float g_bkv[512];
__device__ __nv_bfloat16 g_xe  [(size_t)MM * KE];     // x [hi|lo]
__device__ __nv_bfloat16 g_ae  [(size_t)MM * KE];     // attn out [hi|lo]
__device__ __nv_bfloat16 g_weq [(size_t)CC * KE];     // wq^T [hi|lo]
__device__ __nv_bfloat16 g_wekv[(size_t)512 * KE];    // [wk|wv]^T [hi|lo]
__device__ __nv_bfloat16 g_weo [(size_t)CC * KE];     // wo^T [hi|lo]
__device__ __nv_bfloat16 g_qe  [(size_t)MM * NH * 128];   // Q: [r][h][hi(64)|lo(64)], scaled
__device__ __nv_bfloat16 g_kve [(size_t)MM * 4 * 128];    // K: [r][kvh][hi|lo]
__device__ __nv_bfloat16 g_vt  [(size_t)BB * 4 * 128 * TT]; // V^T: [b][kvh][hi d|lo d][t]

// ---------------- PTX helpers (baseline ISA only) ----------------
__device__ __forceinline__ uint32_t smem_u32(const void* p) {
    uint32_t a;
    asm("{ .reg .u64 t; cvta.to.shared.u64 t, %1; cvt.u32.u64 %0, t; }" : "=r"(a) : "l"(p));
    return a;
}
__device__ __forceinline__ void ldsm_x4(uint32_t* r, uint32_t addr) {
    asm volatile("ldmatrix.sync.aligned.m8n8.x4.shared.b16 {%0,%1,%2,%3}, [%4];"
                 : "=r"(r[0]), "=r"(r[1]), "=r"(r[2]), "=r"(r[3]) : "r"(addr));
}
__device__ __forceinline__ void mma16816(float* d, const uint32_t* a, uint32_t b0, uint32_t b1) {
    asm volatile("mma.sync.aligned.m16n8k16.row.col.f32.bf16.bf16.f32 "
                 "{%0,%1,%2,%3}, {%4,%5,%6,%7}, {%8,%9}, {%0,%1,%2,%3};"
                 : "+f"(d[0]), "+f"(d[1]), "+f"(d[2]), "+f"(d[3])
                 : "r"(a[0]), "r"(a[1]), "r"(a[2]), "r"(a[3]), "r"(b0), "r"(b1));
}
__device__ __forceinline__ void cp16(uint32_t dst, const void* src) {
    asm volatile("cp.async.cg.shared.global [%0], [%1], 16;" :: "r"(dst), "l"(src));
}
#define CP_COMMIT() asm volatile("cp.async.commit_group;" ::: "memory")
#define CP_WAIT1()  asm volatile("cp.async.wait_group 1;" ::: "memory")
#define CP_WAIT0()  asm volatile("cp.async.wait_group 0;" ::: "memory")

__device__ __forceinline__ uint32_t pack_bf2(__nv_bfloat16 x, __nv_bfloat16 y) {
    union { __nv_bfloat162 h; uint32_t u; } c;
    c.h = __nv_bfloat162(x, y);
    return c.u;
}

// ---------------- small kernels ----------------
__global__ void rope_table_kernel() {
    int t = blockIdx.x, p = threadIdx.x;
    float inv = expf(-(float)(2 * p) * ROPE_C);
    float sn, cs;
    sincosf((float)t * inv, &sn, &cs);
    g_rope[t * HD + 2 * p]     = cs;
    g_rope[t * HD + 2 * p + 1] = sn;
}
__global__ void pack_bkv_kernel(const float* __restrict__ bk, const float* __restrict__ bv) {
    int i = threadIdx.x;
    g_bkv[i] = bk[i];
    g_bkv[256 + i] = bv[i];
}
__global__ void convert_a_kernel(const float* __restrict__ src, __nv_bfloat16* __restrict__ dst) {
    for (int idx = blockIdx.x * blockDim.x + threadIdx.x; idx < MM * CC; idx += gridDim.x * blockDim.x) {
        int r = idx >> 10, k = idx & 1023;
        float v = src[idx];
        __nv_bfloat16 hi = __float2bfloat16(v);
        __nv_bfloat16 lo = __float2bfloat16(v - __bfloat162float(hi));
        size_t b = (size_t)r * KE + k;
        dst[b] = hi; dst[b + 1024] = lo;
    }
}
__global__ void convert_w_kernel(const float* __restrict__ w, int N,
                                 __nv_bfloat16* __restrict__ dst, int n_off) {
    for (int idx = blockIdx.x * blockDim.x + threadIdx.x; idx < 1024 * N; idx += gridDim.x * blockDim.x) {
        int k = idx / N, n = idx - k * N;
        float v = w[idx];
        __nv_bfloat16 hi = __float2bfloat16(v);
        __nv_bfloat16 lo = __float2bfloat16(v - __bfloat162float(hi));
        size_t b = (size_t)(n_off + n) * KE + k;
        dst[b] = hi; dst[b + 1024] = lo;
    }
}

// ---------------- HMMA GEMM: 128x128 tile, 8 warps, BK=64, double buffer -----
// 3 logical passes over [hi|lo] operands: (Ahi,Whi), (Ahi,Wlo), (Alo,Whi).
// mode 0: Q proj -> g_qe;  mode 1: KV proj -> g_kve/g_vt;  mode 2: O proj -> fp32 C
#define GSM_TOTAL (4 * 16384)

__device__ __forceinline__ void pass_offsets(int it, int& ka, int& kb) {
    const int pass = it >> 4, kc = it & 15;
    ka = ((pass == 2) ? 1024 : 0) + kc * 64;
    kb = ((pass == 1) ? 1024 : 0) + kc * 64;
}

__device__ __forceinline__ void stage_tile(char* sA, char* sB,
                                           const __nv_bfloat16* Ap, const __nv_bfloat16* Wp,
                                           int ka, int kb, int tid)
{
    #pragma unroll
    for (int i = 0; i < 4; i++) {
        int e   = tid + i * 256;
        int row = e >> 3, ch = e & 7;
        uint4 va = *(const uint4*)(Ap + (size_t)row * KE + ka + ch * 8);
        uint4 vb = *(const uint4*)(Wp + (size_t)row * KE + kb + ch * 8);
        uint32_t sw = row * 128 + ((ch ^ (row & 7)) << 4);
        *(uint4*)(sA + sw) = va;
        *(uint4*)(sB + sw) = vb;
    }
}

__global__ void __launch_bounds__(256, 2)
mma_gemm(const __nv_bfloat16* __restrict__ A, const __nv_bfloat16* __restrict__ W,
         const float* __restrict__ bias, float* __restrict__ C, int ldc,
         int rope_until, int mode)
{
    extern __shared__ char smem[];
    char* bufA[2] = { smem,          smem + 32768 };
    char* bufB[2] = { smem + 16384,  smem + 49152 };
    const uint32_t sb = smem_u32(smem);
    const uint32_t sA32[2] = { sb,          sb + 32768 };
    const uint32_t sB32[2] = { sb + 16384,  sb + 49152 };

    const int tid  = threadIdx.x;
    const int wid  = tid >> 5;
    const int lane = tid & 31;
    const int warpRow = wid & 1;
    const int warpCol = wid >> 1;
    const int row0 = blockIdx.y * 128;
    const int col0 = blockIdx.x * 128;

    const __nv_bfloat16* Ap = A + (size_t)row0 * KE;
    const __nv_bfloat16* Wp = W + (size_t)col0 * KE;

    const int rx   = lane & 7;
    const int rowA = warpRow * 64 + (lane & 7) + ((lane >> 3) & 1) * 8;
    const int hiA  = (lane >> 4) & 1;
    const int rowB = warpCol * 32 + (lane & 7) + ((lane >> 4) & 1) * 8;
    const int hiB  = (lane >> 3) & 1;

    float acc[4][4][4];
    #pragma unroll
    for (int mi = 0; mi < 4; mi++)
        #pragma unroll
        for (int nb = 0; nb < 4; nb++)
            #pragma unroll
            for (int q = 0; q < 4; q++) acc[mi][nb][q] = 0.f;

    {
        int ka, kb2; pass_offsets(0, ka, kb2);
        stage_tile(bufA[0], bufB[0], Ap, Wp, ka, kb2, tid);
    }
    __syncthreads();

    const int NIT = 48;    // 3 passes x 16 chunks
    for (int it = 0; it < NIT; it++) {
        const int cur = it & 1;
        if (it + 1 < NIT) {
            int ka, kb2; pass_offsets(it + 1, ka, kb2);
            stage_tile(bufA[cur ^ 1], bufB[cur ^ 1], Ap, Wp, ka, kb2, tid);
        }

        const uint32_t aBase = sA32[cur] + rowA * 128;
        const uint32_t bBase = sB32[cur] + rowB * 128;
        #pragma unroll
        for (int kk = 0; kk < 4; kk++) {
            uint32_t a[4][4], b[2][4];
            #pragma unroll
            for (int mi = 0; mi < 4; mi++)
                ldsm_x4(a[mi], aBase + mi * 2048 + ((((kk * 2 + hiA) ^ rx)) << 4));
            #pragma unroll
            for (int nj = 0; nj < 2; nj++)
                ldsm_x4(b[nj], bBase + nj * 2048 + ((((kk * 2 + hiB) ^ rx)) << 4));
            #pragma unroll
            for (int mi = 0; mi < 4; mi++) {
                mma16816(acc[mi][0], a[mi], b[0][0], b[0][1]);
                mma16816(acc[mi][1], a[mi], b[0][2], b[0][3]);
                mma16816(acc[mi][2], a[mi], b[1][0], b[1][1]);
                mma16816(acc[mi][3], a[mi], b[1][2], b[1][3]);
            }
        }
        __syncthreads();
    }

    const int g  = lane >> 2;
    const int tg = lane & 3;
    #pragma unroll
    for (int mi = 0; mi < 4; mi++) {
        #pragma unroll
        for (int nb = 0; nb < 4; nb++) {
            const int col = col0 + warpCol * 32 + nb * 8 + tg * 2;
            const float bx = bias[col], by = bias[col + 1];
            const bool rp  = (col < rope_until);
            #pragma unroll
            for (int half = 0; half < 2; half++) {
                const int r = row0 + warpRow * 64 + mi * 16 + g + half * 8;
                float x = acc[mi][nb][half * 2]     + bx;
                float y = acc[mi][nb][half * 2 + 1] + by;
                if (rp) {
                    const int t = r & (TT - 1);
                    float2 cn = *(const float2*)&g_rope[t * HD + (col & (HD - 1))];
                    float e = x, o = y;
                    x = e * cn.x - o * cn.y;
                    y = e * cn.y + o * cn.x;
                }
                if (mode == 2) {
                    *(float2*)(C + (size_t)r * ldc + col) = make_float2(x, y);
                } else if (mode == 0) {
                    x *= 0.125f; y *= 0.125f;
                    __nv_bfloat16 hx = __float2bfloat16(x), hy = __float2bfloat16(y);
                    __nv_bfloat16 lx = __float2bfloat16(x - __bfloat162float(hx));
                    __nv_bfloat16 ly = __float2bfloat16(y - __bfloat162float(hy));
                    const int h = col >> 6, d = col & 63;
                    uint32_t* p = (uint32_t*)&g_qe[((size_t)r * NH + h) * 128 + d];
                    p[0]  = pack_bf2(hx, hy);
                    p[32] = pack_bf2(lx, ly);            // +64 bf16
                } else {
                    __nv_bfloat16 hx = __float2bfloat16(x), hy = __float2bfloat16(y);
                    __nv_bfloat16 lx = __float2bfloat16(x - __bfloat162float(hx));
                    __nv_bfloat16 ly = __float2bfloat16(y - __bfloat162float(hy));
                    if (col < 256) {
                        const int h = col >> 6, d = col & 63;
                        uint32_t* p = (uint32_t*)&g_kve[((size_t)r * 4 + h) * 128 + d];
                        p[0]  = pack_bf2(hx, hy);
                        p[32] = pack_bf2(lx, ly);
                    } else {
                        const int cv = col - 256, h = cv >> 6, d = cv & 63;
                        const int bb = r >> 11, t = r & (TT - 1);
                        __nv_bfloat16* p = &g_vt[(((size_t)(bb * 4 + h) * 128) + d) * TT + t];
                        p[0]        = hx;   // vhi[d][t]
                        p[TT]       = hy;   // vhi[d+1][t]
                        p[64 * TT]  = lx;   // vlo[d][t]
                        p[65 * TT]  = ly;
                    }
                }
            }
        }
    }
}

// ---------------- tensor-core flash attention -------------------------------
// 256 thr = 8 warps, each warp: 16 q-rows. Q-tile 128, KV-chunk 64.
// smem: Qs 128x256B (hi|lo, swz) + K[2] 64x256B + Vt[2] 128x128B = 96KB.
#define AT_QS   0
#define AT_K0   32768
#define AT_V0   65536
#define AT_TOTAL 98304

__device__ __forceinline__ void load_kv_chunk(uint32_t sb, int buf, int b, int kvh,
                                              int t0, int tid)
{
    const __nv_bfloat16* kg = &g_kve[((size_t)(b * TT + t0) * 4 + kvh) * 128];
    const uint32_t kdst = sb + AT_K0 + buf * 16384;
    #pragma unroll
    for (int i = 0; i < 4; i++) {
        int e = tid + i * 256, c = e >> 4, ch = e & 15;
        cp16(kdst + c * 256 + (((ch & 8) | ((ch ^ c) & 7)) << 4), kg + (size_t)c * 512 + ch * 8);
    }
    const __nv_bfloat16* vg = &g_vt[(size_t)(b * 4 + kvh) * 128 * TT + t0];
    const uint32_t vdst = sb + AT_V0 + buf * 16384;
    #pragma unroll
    for (int i = 0; i < 4; i++) {
        int e = tid + i * 256, d = e >> 3, ch = e & 7;
        cp16(vdst + d * 128 + (((ch ^ d) & 7) << 4), vg + (size_t)d * TT + ch * 8);
    }
}

__global__ void __launch_bounds__(256, 2)
attn_kernel()
{
    extern __shared__ char smem[];
    const uint32_t sb = smem_u32(smem);

    const int b  = blockIdx.z;
    const int h  = blockIdx.y;
    const int qt = gridDim.x - 1 - blockIdx.x;   // heavy tiles first
    const int kvh = h >> 2;
    const int tid  = threadIdx.x;
    const int w    = tid >> 5;
    const int lane = tid & 31;
    const int g    = lane >> 2;
    const int tg   = lane & 3;

    // load Q tile (once)
    {
        const __nv_bfloat16* qg = &g_qe[((size_t)(b * TT + qt * 128) * NH + h) * 128];
        #pragma unroll
        for (int i = 0; i < 8; i++) {
            int e = tid + i * 256, r = e >> 4, ch = e & 15;
            cp16(sb + AT_QS + r * 256 + (((ch & 8) | ((ch ^ r) & 7)) << 4),
                 qg + (size_t)r * (NH * 128) + ch * 8);
        }
    }
    CP_COMMIT();
    load_kv_chunk(sb, 0, b, kvh, 0, tid);
    CP_COMMIT();

    const int qrow = w * 16 + (lane & 7) + ((lane >> 3) & 1) * 8;
    const int hiA  = (lane >> 4) & 1;
    const int brow = (lane & 7) + ((lane >> 4) & 1) * 8;
    const int hiB  = (lane >> 3) & 1;
    const uint32_t aBase = sb + AT_QS + qrow * 256;

    float m0 = -3.0e38f, m1 = -3.0e38f, l0 = 0.f, l1 = 0.f;
    float ov[8][4];
    #pragma unroll
    for (int nt = 0; nt < 8; nt++)
        #pragma unroll
        for (int q = 0; q < 4; q++) ov[nt][q] = 0.f;

    const int jend = 2 * qt + 1;
    for (int jt = 0; jt <= jend; jt++) {
        if (jt < jend) { load_kv_chunk(sb, (jt + 1) & 1, b, kvh, (jt + 1) * 64, tid); CP_COMMIT(); CP_WAIT1(); }
        else CP_WAIT0();
        __syncthreads();

        const int buf = jt & 1;
        const uint32_t kBase = sb + AT_K0 + buf * 16384;
        const uint32_t vBase = sb + AT_V0 + buf * 16384;

        // ---- S = Qe @ Ke^T (3-pass split) ----
        float sv[8][4];
        #pragma unroll
        for (int nt = 0; nt < 8; nt++)
            #pragma unroll
            for (int q = 0; q < 4; q++) sv[nt][q] = 0.f;

        #pragma unroll
        for (int pass = 0; pass < 3; pass++) {
            const int qo = (pass == 2) ? 8 : 0;
            const int ko = (pass == 1) ? 8 : 0;
            #pragma unroll
            for (int kc = 0; kc < 4; kc++) {
                uint32_t a[4];
                const int chA = qo + 2 * kc + hiA;
                ldsm_x4(a, aBase + (((chA & 8) | ((chA ^ qrow) & 7)) << 4));
                #pragma unroll
                for (int nt2 = 0; nt2 < 4; nt2++) {
                    uint32_t bf[4];
                    const int c = nt2 * 16 + brow;
                    const int chB = ko + 2 * kc + hiB;
                    ldsm_x4(bf, kBase + c * 256 + (((chB & 8) | ((chB ^ c) & 7)) << 4));
                    mma16816(sv[nt2 * 2],     a, bf[0], bf[1]);
                    mma16816(sv[nt2 * 2 + 1], a, bf[2], bf[3]);
                }
            }
        }

        // ---- causal mask ----
        const int kc0 = jt * 64;
        if (kc0 + 63 > qt * 128 + w * 16) {
            #pragma unroll
            for (int nt = 0; nt < 8; nt++)
                #pragma unroll
                for (int q = 0; q < 4; q++) {
                    const int row = qt * 128 + w * 16 + g + 8 * (q >> 1);
                    const int col = kc0 + nt * 8 + tg * 2 + (q & 1);
                    if (col > row) sv[nt][q] = -1.0e30f;
                }
        }

        // ---- online softmax ----
        float mx0 = -3.0e38f, mx1 = -3.0e38f;
        #pragma unroll
        for (int nt = 0; nt < 8; nt++) {
            mx0 = fmaxf(mx0, fmaxf(sv[nt][0], sv[nt][1]));
            mx1 = fmaxf(mx1, fmaxf(sv[nt][2], sv[nt][3]));
        }
        mx0 = fmaxf(mx0, __shfl_xor_sync(0xffffffffu, mx0, 1));
        mx0 = fmaxf(mx0, __shfl_xor_sync(0xffffffffu, mx0, 2));
        mx1 = fmaxf(mx1, __shfl_xor_sync(0xffffffffu, mx1, 1));
        mx1 = fmaxf(mx1, __shfl_xor_sync(0xffffffffu, mx1, 2));
        const float mn0 = fmaxf(m0, mx0), mn1 = fmaxf(m1, mx1);
        const float al0 = __expf(m0 - mn0), al1 = __expf(m1 - mn1);
        float rs0 = 0.f, rs1 = 0.f;
        #pragma unroll
        for (int nt = 0; nt < 8; nt++) {
            sv[nt][0] = __expf(sv[nt][0] - mn0); rs0 += sv[nt][0];
            sv[nt][1] = __expf(sv[nt][1] - mn0); rs0 += sv[nt][1];
            sv[nt][2] = __expf(sv[nt][2] - mn1); rs1 += sv[nt][2];
            sv[nt][3] = __expf(sv[nt][3] - mn1); rs1 += sv[nt][3];
        }
        rs0 += __shfl_xor_sync(0xffffffffu, rs0, 1);
        rs0 += __shfl_xor_sync(0xffffffffu, rs0, 2);
        rs1 += __shfl_xor_sync(0xffffffffu, rs1, 1);
        rs1 += __shfl_xor_sync(0xffffffffu, rs1, 2);
        l0 = l0 * al0 + rs0; l1 = l1 * al1 + rs1;
        m0 = mn0; m1 = mn1;
        #pragma unroll
        for (int nt = 0; nt < 8; nt++) {
            ov[nt][0] *= al0; ov[nt][1] *= al0;
            ov[nt][2] *= al1; ov[nt][3] *= al1;
        }

        // ---- P hi-fragments ----
        uint32_t aph[4][4];
        #pragma unroll
        for (int cc = 0; cc < 4; cc++) {
            aph[cc][0] = pack_bf2(__float2bfloat16(sv[2*cc][0]),   __float2bfloat16(sv[2*cc][1]));
            aph[cc][1] = pack_bf2(__float2bfloat16(sv[2*cc][2]),   __float2bfloat16(sv[2*cc][3]));
            aph[cc][2] = pack_bf2(__float2bfloat16(sv[2*cc+1][0]), __float2bfloat16(sv[2*cc+1][1]));
            aph[cc][3] = pack_bf2(__float2bfloat16(sv[2*cc+1][2]), __float2bfloat16(sv[2*cc+1][3]));
        }

        // ---- O += P @ V (3-pass split) ----
        #pragma unroll
        for (int pass = 0; pass < 3; pass++) {
            const int vro = (pass == 1) ? 64 : 0;
            #pragma unroll
            for (int cc = 0; cc < 4; cc++) {
                uint32_t a[4];
                if (pass < 2) {
                    a[0] = aph[cc][0]; a[1] = aph[cc][1]; a[2] = aph[cc][2]; a[3] = aph[cc][3];
                } else {
                    #pragma unroll
                    for (int q2 = 0; q2 < 2; q2++) {
                        float p0 = sv[2*cc][q2*2],   p1 = sv[2*cc][q2*2+1];
                        float p2 = sv[2*cc+1][q2*2], p3 = sv[2*cc+1][q2*2+1];
                        __nv_bfloat16 h0 = __float2bfloat16(p0), h1 = __float2bfloat16(p1);
                        __nv_bfloat16 h2 = __float2bfloat16(p2), h3 = __float2bfloat16(p3);
                        a[q2]     = pack_bf2(__float2bfloat16(p0 - __bfloat162float(h0)),
                                             __float2bfloat16(p1 - __bfloat162float(h1)));
                        a[q2 + 2] = pack_bf2(__float2bfloat16(p2 - __bfloat162float(h2)),
                                             __float2bfloat16(p3 - __bfloat162float(h3)));
                    }
                }
                #pragma unroll
                for (int nt2 = 0; nt2 < 4; nt2++) {
                    uint32_t bf[4];
                    const int d = vro + nt2 * 16 + brow;
                    const int chV = 2 * cc + hiB;
                    ldsm_x4(bf, vBase + d * 128 + (((chV ^ d) & 7) << 4));
                    mma16816(ov[nt2 * 2],     a, bf[0], bf[1]);
                    mma16816(ov[nt2 * 2 + 1], a, bf[2], bf[3]);
                }
            }
        }
        __syncthreads();
    }

    // ---- epilogue: normalize, write [hi|lo] A-layout for O-proj ----
    const float i0 = 1.f / l0, i1 = 1.f / l1;
    const size_t r0g = (size_t)(b * TT + qt * 128 + w * 16 + g);
    #pragma unroll
    for (int nt = 0; nt < 8; nt++) {
        const int dg = h * 64 + nt * 8 + tg * 2;
        #pragma unroll
        for (int half = 0; half < 2; half++) {
            const float x = ov[nt][half * 2]     * (half ? i1 : i0);
            const float y = ov[nt][half * 2 + 1] * (half ? i1 : i0);
            __nv_bfloat16 hx = __float2bfloat16(x), hy = __float2bfloat16(y);
            __nv_bfloat16 lx = __float2bfloat16(x - __bfloat162float(hx));
            __nv_bfloat16 ly = __float2bfloat16(y - __bfloat162float(hy));
            uint32_t* p = (uint32_t*)&g_ae[(r0g + half * 8) * KE + dg];
            p[0]   = pack_bf2(hx, hy);
            p[512] = pack_bf2(lx, ly);      // +1024 bf16
        }
    }
}

// ---------------- launch ----------------
extern "C" void kernel_launch(void* const* d_in, const int* in_sizes, int n_in,
                              void* d_out, int out_size)
{
    (void)in_sizes; (void)n_in; (void)out_size;
    const float* x  = (const float*)d_in[0];
    const float* wq = (const float*)d_in[1];
    const float* bq = (const float*)d_in[2];
    const float* wk = (const float*)d_in[3];
    const float* bk = (const float*)d_in[4];
    const float* wv = (const float*)d_in[5];
    const float* bv = (const float*)d_in[6];
    const float* wo = (const float*)d_in[7];
    const float* bo = (const float*)d_in[8];
    float* out = (float*)d_out;

    float* bkv;
    __nv_bfloat16 *xe, *ae, *weq, *wekv, *weo;
    cudaGetSymbolAddress((void**)&bkv,  g_bkv);
    cudaGetSymbolAddress((void**)&xe,   g_xe);
    cudaGetSymbolAddress((void**)&ae,   g_ae);
    cudaGetSymbolAddress((void**)&weq,  g_weq);
    cudaGetSymbolAddress((void**)&wekv, g_wekv);
    cudaGetSymbolAddress((void**)&weo,  g_weo);

    cudaFuncSetAttribute(mma_gemm,    cudaFuncAttributeMaxDynamicSharedMemorySize, GSM_TOTAL);
    cudaFuncSetAttribute(attn_kernel, cudaFuncAttributeMaxDynamicSharedMemorySize, AT_TOTAL);

    rope_table_kernel<<<TT, 32>>>();
    pack_bkv_kernel<<<1, 256>>>(bk, bv);
    convert_a_kernel<<<2048, 256>>>(x, xe);
    convert_w_kernel<<<1024, 256>>>(wq, 1024, weq, 0);
    convert_w_kernel<<<512, 256>>>(wk, 256, wekv, 0);
    convert_w_kernel<<<512, 256>>>(wv, 256, wekv, 256);
    convert_w_kernel<<<1024, 256>>>(wo, 1024, weo, 0);

    // Q proj -> g_qe (mode 0); K|V proj -> g_kve/g_vt (mode 1)
    mma_gemm<<<dim3(8, 32), 256, GSM_TOTAL>>>(xe, weq, bq, nullptr, 0, CC, 0);
    mma_gemm<<<dim3(4, 32), 256, GSM_TOTAL>>>(xe, wekv, bkv, nullptr, 0, 256, 1);

    attn_kernel<<<dim3(TT / 128, NH, BB), 256, AT_TOTAL>>>();

    // O proj -> fp32 out (mode 2)
    mma_gemm<<<dim3(8, 32), 256, GSM_TOTAL>>>(ae, weo, bo, out, CC, 0, 2);
}

// round 14
// speedup vs baseline: 2.5290x; 1.1014x over previous
#include <cuda_runtime.h>
#include <cuda_bf16.h>
#include <cstdint>
#include <cstddef>

// ---------------- problem constants ----------------
#define BB   2
#define TT   2048
#define CC   1024
#define NH   16
#define HD   64
#define MM   (BB * TT)        // 4096
#define KE   2048             // [hi(1024) | lo(1024)] operand layout
#define ROPE_C 0.14391156831212787f

// ---------------- scratch ----------------
__device__ float g_rope[TT * HD];
__device__ float g_bkv[512];
__device__ __nv_bfloat16 g_xe  [(size_t)MM * KE];     // x [hi|lo]
__device__ __nv_bfloat16 g_ae  [(size_t)MM * KE];     // attn out [hi|lo]
__device__ __nv_bfloat16 g_weq [(size_t)CC * KE];     // wq^T [hi|lo]
__device__ __nv_bfloat16 g_wekv[(size_t)512 * KE];    // [wk|wv]^T [hi|lo]
__device__ __nv_bfloat16 g_weo [(size_t)CC * KE];     // wo^T [hi|lo]
__device__ __nv_bfloat16 g_qe  [(size_t)MM * NH * 128];   // Q: [r][h][hi(64)|lo(64)], scaled
__device__ __nv_bfloat16 g_kve [(size_t)MM * 4 * 128];    // K: [r][kvh][hi|lo]
__device__ __nv_bfloat16 g_vt  [(size_t)BB * 4 * 128 * TT]; // V^T: [b][kvh][hi d|lo d][t]

// ---------------- PTX helpers (baseline ISA only) ----------------
__device__ __forceinline__ uint32_t smem_u32(const void* p) {
    uint32_t a;
    asm("{ .reg .u64 t; cvta.to.shared.u64 t, %1; cvt.u32.u64 %0, t; }" : "=r"(a) : "l"(p));
    return a;
}
__device__ __forceinline__ void ldsm_x4(uint32_t* r, uint32_t addr) {
    asm volatile("ldmatrix.sync.aligned.m8n8.x4.shared.b16 {%0,%1,%2,%3}, [%4];"
                 : "=r"(r[0]), "=r"(r[1]), "=r"(r[2]), "=r"(r[3]) : "r"(addr));
}
__device__ __forceinline__ void mma16816(float* d, const uint32_t* a, uint32_t b0, uint32_t b1) {
    asm volatile("mma.sync.aligned.m16n8k16.row.col.f32.bf16.bf16.f32 "
                 "{%0,%1,%2,%3}, {%4,%5,%6,%7}, {%8,%9}, {%0,%1,%2,%3};"
                 : "+f"(d[0]), "+f"(d[1]), "+f"(d[2]), "+f"(d[3])
                 : "r"(a[0]), "r"(a[1]), "r"(a[2]), "r"(a[3]), "r"(b0), "r"(b1));
}
__device__ __forceinline__ void cp16(uint32_t dst, const void* src) {
    asm volatile("cp.async.cg.shared.global [%0], [%1], 16;" :: "r"(dst), "l"(src));
}
#define CP_COMMIT() asm volatile("cp.async.commit_group;" ::: "memory")
#define CP_WAIT1()  asm volatile("cp.async.wait_group 1;" ::: "memory")
#define CP_WAIT0()  asm volatile("cp.async.wait_group 0;" ::: "memory")

__device__ __forceinline__ uint32_t pack_bf2(__nv_bfloat16 x, __nv_bfloat16 y) {
    union { __nv_bfloat162 h; uint32_t u; } c;
    c.h = __nv_bfloat162(x, y);
    return c.u;
}

// ---------------- merged prep kernel ----------------------------------------
// block ranges:
//   [0,256)     wq transpose tiles (16k x 16n of 64x64)
//   [256,320)   wk tiles (16 x 4)
//   [320,384)   wv tiles (16 x 4)
//   [384,640)   wo tiles
//   [640,2688)  x hi/lo split (8 elems/thread)
//   [2688,2944) rope table
//   [2944,2946) bias pack
__global__ void __launch_bounds__(256)
prep_kernel(const float* __restrict__ x,
            const float* __restrict__ wq, const float* __restrict__ wk,
            const float* __restrict__ wv, const float* __restrict__ wo,
            const float* __restrict__ bk, const float* __restrict__ bv)
{
    // NOTE: row stride 68 floats = 272 B = multiple of 16 -> float4 ops aligned.
    __shared__ float sm[64][68];
    const int blk = blockIdx.x;
    const int tid = threadIdx.x;

    if (blk < 640) {
        const float* w; __nv_bfloat16* dst; int N, n_off, tt;
        if (blk < 256)      { w = wq; dst = g_weq;  N = 1024; n_off = 0;   tt = blk; }
        else if (blk < 320) { w = wk; dst = g_wekv; N = 256;  n_off = 0;   tt = blk - 256; }
        else if (blk < 384) { w = wv; dst = g_wekv; N = 256;  n_off = 256; tt = blk - 320; }
        else                { w = wo; dst = g_weo;  N = 1024; n_off = 0;   tt = blk - 384; }
        const int tiles_n = N >> 6;
        const int k0 = (tt / tiles_n) << 6;
        const int n0 = (tt % tiles_n) << 6;
        #pragma unroll
        for (int i = 0; i < 4; i++) {
            int e = tid + i * 256;
            int kk = e >> 4, seg = e & 15;
            *(float4*)&sm[kk][seg * 4] = *(const float4*)&w[(size_t)(k0 + kk) * N + n0 + seg * 4];
        }
        __syncthreads();
        const int n = tid >> 2, seg = tid & 3;
        __align__(16) __nv_bfloat16 hi16[16];
        __align__(16) __nv_bfloat16 lo16[16];
        #pragma unroll
        for (int j = 0; j < 16; j++) {
            float v = sm[seg * 16 + j][n];
            __nv_bfloat16 h = __float2bfloat16(v);
            hi16[j] = h;
            lo16[j] = __float2bfloat16(v - __bfloat162float(h));
        }
        __nv_bfloat16* base = dst + (size_t)(n_off + n0 + n) * KE + k0 + seg * 16;
        *(uint4*)(base)        = *(uint4*)&hi16[0];
        *(uint4*)(base + 8)    = *(uint4*)&hi16[8];
        *(uint4*)(base + 1024) = *(uint4*)&lo16[0];
        *(uint4*)(base + 1032) = *(uint4*)&lo16[8];
    } else if (blk < 2688) {
        const int idx = (blk - 640) * 2048 + tid * 8;   // element index into MM*CC
        const int r = idx >> 10, k = idx & 1023;
        float4 v0 = *(const float4*)&x[idx];
        float4 v1 = *(const float4*)&x[idx + 4];
        float f[8] = { v0.x, v0.y, v0.z, v0.w, v1.x, v1.y, v1.z, v1.w };
        __align__(16) __nv_bfloat16 hi[8];
        __align__(16) __nv_bfloat16 lo[8];
        #pragma unroll
        for (int j = 0; j < 8; j++) {
            hi[j] = __float2bfloat16(f[j]);
            lo[j] = __float2bfloat16(f[j] - __bfloat162float(hi[j]));
        }
        __nv_bfloat16* base = g_xe + (size_t)r * KE + k;
        *(uint4*)(base)        = *(uint4*)&hi[0];
        *(uint4*)(base + 1024) = *(uint4*)&lo[0];
    } else if (blk < 2944) {
        const int id = (blk - 2688) * 256 + tid;    // 0..65535
        const int t = id >> 5, p = id & 31;
        float inv = expf(-(float)(2 * p) * ROPE_C);
        float sn, cs;
        sincosf((float)t * inv, &sn, &cs);
        g_rope[t * HD + 2 * p]     = cs;
        g_rope[t * HD + 2 * p + 1] = sn;
    } else {
        const int i = (blk - 2944) * 256 + tid;     // 0..511
        g_bkv[i] = (i < 256) ? bk[i] : bv[i - 256];
    }
}

// ---------------- HMMA GEMM: 128x128 tile, 8 warps, BK=64, double buffer -----
// 3 logical passes over [hi|lo] operands: (Ahi,Whi), (Ahi,Wlo), (Alo,Whi).
// mode 0: Q proj -> g_qe;  mode 1: KV proj -> g_kve/g_vt;  mode 2: O proj -> fp32 C
#define GSM_TOTAL (4 * 16384)

__device__ __forceinline__ void pass_offsets(int it, int& ka, int& kb) {
    const int pass = it >> 4, kc = it & 15;
    ka = ((pass == 2) ? 1024 : 0) + kc * 64;
    kb = ((pass == 1) ? 1024 : 0) + kc * 64;
}

__device__ __forceinline__ void stage_tile(char* sA, char* sB,
                                           const __nv_bfloat16* Ap, const __nv_bfloat16* Wp,
                                           int ka, int kb, int tid)
{
    #pragma unroll
    for (int i = 0; i < 4; i++) {
        int e   = tid + i * 256;
        int row = e >> 3, ch = e & 7;
        uint4 va = *(const uint4*)(Ap + (size_t)row * KE + ka + ch * 8);
        uint4 vb = *(const uint4*)(Wp + (size_t)row * KE + kb + ch * 8);
        uint32_t sw = row * 128 + ((ch ^ (row & 7)) << 4);
        *(uint4*)(sA + sw) = va;
        *(uint4*)(sB + sw) = vb;
    }
}

__global__ void __launch_bounds__(256, 2)
mma_gemm(const __nv_bfloat16* __restrict__ A, const __nv_bfloat16* __restrict__ W,
         const float* __restrict__ bias, float* __restrict__ C, int ldc,
         int rope_until, int mode)
{
    extern __shared__ char smem[];
    char* bufA[2] = { smem,          smem + 32768 };
    char* bufB[2] = { smem + 16384,  smem + 49152 };
    const uint32_t sb = smem_u32(smem);
    const uint32_t sA32[2] = { sb,          sb + 32768 };
    const uint32_t sB32[2] = { sb + 16384,  sb + 49152 };

    const int tid  = threadIdx.x;
    const int wid  = tid >> 5;
    const int lane = tid & 31;
    const int warpRow = wid & 1;
    const int warpCol = wid >> 1;
    const int row0 = blockIdx.y * 128;
    const int col0 = blockIdx.x * 128;

    const __nv_bfloat16* Ap = A + (size_t)row0 * KE;
    const __nv_bfloat16* Wp = W + (size_t)col0 * KE;

    const int rx   = lane & 7;
    const int rowA = warpRow * 64 + (lane & 7) + ((lane >> 3) & 1) * 8;
    const int hiA  = (lane >> 4) & 1;
    const int rowB = warpCol * 32 + (lane & 7) + ((lane >> 4) & 1) * 8;
    const int hiB  = (lane >> 3) & 1;

    float acc[4][4][4];
    #pragma unroll
    for (int mi = 0; mi < 4; mi++)
        #pragma unroll
        for (int nb = 0; nb < 4; nb++)
            #pragma unroll
            for (int q = 0; q < 4; q++) acc[mi][nb][q] = 0.f;

    {
        int ka, kb2; pass_offsets(0, ka, kb2);
        stage_tile(bufA[0], bufB[0], Ap, Wp, ka, kb2, tid);
    }
    __syncthreads();

    const int NIT = 48;    // 3 passes x 16 chunks
    for (int it = 0; it < NIT; it++) {
        const int cur = it & 1;
        if (it + 1 < NIT) {
            int ka, kb2; pass_offsets(it + 1, ka, kb2);
            stage_tile(bufA[cur ^ 1], bufB[cur ^ 1], Ap, Wp, ka, kb2, tid);
        }

        const uint32_t aBase = sA32[cur] + rowA * 128;
        const uint32_t bBase = sB32[cur] + rowB * 128;
        #pragma unroll
        for (int kk = 0; kk < 4; kk++) {
            uint32_t a[4][4], b[2][4];
            #pragma unroll
            for (int mi = 0; mi < 4; mi++)
                ldsm_x4(a[mi], aBase + mi * 2048 + ((((kk * 2 + hiA) ^ rx)) << 4));
            #pragma unroll
            for (int nj = 0; nj < 2; nj++)
                ldsm_x4(b[nj], bBase + nj * 2048 + ((((kk * 2 + hiB) ^ rx)) << 4));
            #pragma unroll
            for (int mi = 0; mi < 4; mi++) {
                mma16816(acc[mi][0], a[mi], b[0][0], b[0][1]);
                mma16816(acc[mi][1], a[mi], b[0][2], b[0][3]);
                mma16816(acc[mi][2], a[mi], b[1][0], b[1][1]);
                mma16816(acc[mi][3], a[mi], b[1][2], b[1][3]);
            }
        }
        __syncthreads();
    }

    const int g  = lane >> 2;
    const int tg = lane & 3;
    #pragma unroll
    for (int mi = 0; mi < 4; mi++) {
        #pragma unroll
        for (int nb = 0; nb < 4; nb++) {
            const int col = col0 + warpCol * 32 + nb * 8 + tg * 2;
            const float bx = bias[col], by = bias[col + 1];
            const bool rp  = (col < rope_until);
            #pragma unroll
            for (int half = 0; half < 2; half++) {
                const int r = row0 + warpRow * 64 + mi * 16 + g + half * 8;
                float x = acc[mi][nb][half * 2]     + bx;
                float y = acc[mi][nb][half * 2 + 1] + by;
                if (rp) {
                    const int t = r & (TT - 1);
                    float2 cn = *(const float2*)&g_rope[t * HD + (col & (HD - 1))];
                    float e = x, o = y;
                    x = e * cn.x - o * cn.y;
                    y = e * cn.y + o * cn.x;
                }
                if (mode == 2) {
                    *(float2*)(C + (size_t)r * ldc + col) = make_float2(x, y);
                } else if (mode == 0) {
                    x *= 0.125f; y *= 0.125f;
                    __nv_bfloat16 hx = __float2bfloat16(x), hy = __float2bfloat16(y);
                    __nv_bfloat16 lx = __float2bfloat16(x - __bfloat162float(hx));
                    __nv_bfloat16 ly = __float2bfloat16(y - __bfloat162float(hy));
                    const int h = col >> 6, d = col & 63;
                    uint32_t* p = (uint32_t*)&g_qe[((size_t)r * NH + h) * 128 + d];
                    p[0]  = pack_bf2(hx, hy);
                    p[32] = pack_bf2(lx, ly);            // +64 bf16
                } else {
                    __nv_bfloat16 hx = __float2bfloat16(x), hy = __float2bfloat16(y);
                    __nv_bfloat16 lx = __float2bfloat16(x - __bfloat162float(hx));
                    __nv_bfloat16 ly = __float2bfloat16(y - __bfloat162float(hy));
                    if (col < 256) {
                        const int h = col >> 6, d = col & 63;
                        uint32_t* p = (uint32_t*)&g_kve[((size_t)r * 4 + h) * 128 + d];
                        p[0]  = pack_bf2(hx, hy);
                        p[32] = pack_bf2(lx, ly);
                    } else {
                        const int cv = col - 256, h = cv >> 6, d = cv & 63;
                        const int bb = r >> 11, t = r & (TT - 1);
                        __nv_bfloat16* p = &g_vt[(((size_t)(bb * 4 + h) * 128) + d) * TT + t];
                        p[0]        = hx;   // vhi[d][t]
                        p[TT]       = hy;   // vhi[d+1][t]
                        p[64 * TT]  = lx;   // vlo[d][t]
                        p[65 * TT]  = ly;
                    }
                }
            }
        }
    }
}

// ---------------- tensor-core flash attention -------------------------------
// 256 thr = 8 warps, each warp: 16 q-rows. Q-tile 128, KV-chunk 64.
// smem: Qs 128x256B (hi|lo, swz) + K[2] 64x256B + Vt[2] 128x128B = 96KB.
#define AT_QS   0
#define AT_K0   32768
#define AT_V0   65536
#define AT_TOTAL 98304

__device__ __forceinline__ void load_kv_chunk(uint32_t sb, int buf, int b, int kvh,
                                              int t0, int tid)
{
    const __nv_bfloat16* kg = &g_kve[((size_t)(b * TT + t0) * 4 + kvh) * 128];
    const uint32_t kdst = sb + AT_K0 + buf * 16384;
    #pragma unroll
    for (int i = 0; i < 4; i++) {
        int e = tid + i * 256, c = e >> 4, ch = e & 15;
        cp16(kdst + c * 256 + (((ch & 8) | ((ch ^ c) & 7)) << 4), kg + (size_t)c * 512 + ch * 8);
    }
    const __nv_bfloat16* vg = &g_vt[(size_t)(b * 4 + kvh) * 128 * TT + t0];
    const uint32_t vdst = sb + AT_V0 + buf * 16384;
    #pragma unroll
    for (int i = 0; i < 4; i++) {
        int e = tid + i * 256, d = e >> 3, ch = e & 7;
        cp16(vdst + d * 128 + (((ch ^ d) & 7) << 4), vg + (size_t)d * TT + ch * 8);
    }
}

__global__ void __launch_bounds__(256, 2)
attn_kernel()
{
    extern __shared__ char smem[];
    const uint32_t sb = smem_u32(smem);

    const int b  = blockIdx.z;
    const int h  = blockIdx.y;
    const int qt = gridDim.x - 1 - blockIdx.x;   // heavy tiles first
    const int kvh = h >> 2;
    const int tid  = threadIdx.x;
    const int w    = tid >> 5;
    const int lane = tid & 31;
    const int g    = lane >> 2;
    const int tg   = lane & 3;

    // load Q tile (once)
    {
        const __nv_bfloat16* qg = &g_qe[((size_t)(b * TT + qt * 128) * NH + h) * 128];
        #pragma unroll
        for (int i = 0; i < 8; i++) {
            int e = tid + i * 256, r = e >> 4, ch = e & 15;
            cp16(sb + AT_QS + r * 256 + (((ch & 8) | ((ch ^ r) & 7)) << 4),
                 qg + (size_t)r * (NH * 128) + ch * 8);
        }
    }
    CP_COMMIT();
    load_kv_chunk(sb, 0, b, kvh, 0, tid);
    CP_COMMIT();

    const int qrow = w * 16 + (lane & 7) + ((lane >> 3) & 1) * 8;
    const int hiA  = (lane >> 4) & 1;
    const int brow = (lane & 7) + ((lane >> 4) & 1) * 8;
    const int hiB  = (lane >> 3) & 1;
    const uint32_t aBase = sb + AT_QS + qrow * 256;

    float m0 = -3.0e38f, m1 = -3.0e38f, l0 = 0.f, l1 = 0.f;
    float ov[8][4];
    #pragma unroll
    for (int nt = 0; nt < 8; nt++)
        #pragma unroll
        for (int q = 0; q < 4; q++) ov[nt][q] = 0.f;

    const int jend = 2 * qt + 1;
    for (int jt = 0; jt <= jend; jt++) {
        if (jt < jend) { load_kv_chunk(sb, (jt + 1) & 1, b, kvh, (jt + 1) * 64, tid); CP_COMMIT(); CP_WAIT1(); }
        else CP_WAIT0();
        __syncthreads();

        const int buf = jt & 1;
        const uint32_t kBase = sb + AT_K0 + buf * 16384;
        const uint32_t vBase = sb + AT_V0 + buf * 16384;

        // ---- S = Qe @ Ke^T (3-pass split) ----
        float sv[8][4];
        #pragma unroll
        for (int nt = 0; nt < 8; nt++)
            #pragma unroll
            for (int q = 0; q < 4; q++) sv[nt][q] = 0.f;

        #pragma unroll
        for (int pass = 0; pass < 3; pass++) {
            const int qo = (pass == 2) ? 8 : 0;
            const int ko = (pass == 1) ? 8 : 0;
            #pragma unroll
            for (int kc = 0; kc < 4; kc++) {
                uint32_t a[4];
                const int chA = qo + 2 * kc + hiA;
                ldsm_x4(a, aBase + (((chA & 8) | ((chA ^ qrow) & 7)) << 4));
                #pragma unroll
                for (int nt2 = 0; nt2 < 4; nt2++) {
                    uint32_t bf[4];
                    const int c = nt2 * 16 + brow;
                    const int chB = ko + 2 * kc + hiB;
                    ldsm_x4(bf, kBase + c * 256 + (((chB & 8) | ((chB ^ c) & 7)) << 4));
                    mma16816(sv[nt2 * 2],     a, bf[0], bf[1]);
                    mma16816(sv[nt2 * 2 + 1], a, bf[2], bf[3]);
                }
            }
        }

        // ---- causal mask ----
        const int kc0 = jt * 64;
        if (kc0 + 63 > qt * 128 + w * 16) {
            #pragma unroll
            for (int nt = 0; nt < 8; nt++)
                #pragma unroll
                for (int q = 0; q < 4; q++) {
                    const int row = qt * 128 + w * 16 + g + 8 * (q >> 1);
                    const int col = kc0 + nt * 8 + tg * 2 + (q & 1);
                    if (col > row) sv[nt][q] = -1.0e30f;
                }
        }

        // ---- online softmax ----
        float mx0 = -3.0e38f, mx1 = -3.0e38f;
        #pragma unroll
        for (int nt = 0; nt < 8; nt++) {
            mx0 = fmaxf(mx0, fmaxf(sv[nt][0], sv[nt][1]));
            mx1 = fmaxf(mx1, fmaxf(sv[nt][2], sv[nt][3]));
        }
        mx0 = fmaxf(mx0, __shfl_xor_sync(0xffffffffu, mx0, 1));
        mx0 = fmaxf(mx0, __shfl_xor_sync(0xffffffffu, mx0, 2));
        mx1 = fmaxf(mx1, __shfl_xor_sync(0xffffffffu, mx1, 1));
        mx1 = fmaxf(mx1, __shfl_xor_sync(0xffffffffu, mx1, 2));
        const float mn0 = fmaxf(m0, mx0), mn1 = fmaxf(m1, mx1);
        const float al0 = __expf(m0 - mn0), al1 = __expf(m1 - mn1);
        float rs0 = 0.f, rs1 = 0.f;
        #pragma unroll
        for (int nt = 0; nt < 8; nt++) {
            sv[nt][0] = __expf(sv[nt][0] - mn0); rs0 += sv[nt][0];
            sv[nt][1] = __expf(sv[nt][1] - mn0); rs0 += sv[nt][1];
            sv[nt][2] = __expf(sv[nt][2] - mn1); rs1 += sv[nt][2];
            sv[nt][3] = __expf(sv[nt][3] - mn1); rs1 += sv[nt][3];
        }
        rs0 += __shfl_xor_sync(0xffffffffu, rs0, 1);
        rs0 += __shfl_xor_sync(0xffffffffu, rs0, 2);
        rs1 += __shfl_xor_sync(0xffffffffu, rs1, 1);
        rs1 += __shfl_xor_sync(0xffffffffu, rs1, 2);
        l0 = l0 * al0 + rs0; l1 = l1 * al1 + rs1;
        m0 = mn0; m1 = mn1;
        #pragma unroll
        for (int nt = 0; nt < 8; nt++) {
            ov[nt][0] *= al0; ov[nt][1] *= al0;
            ov[nt][2] *= al1; ov[nt][3] *= al1;
        }

        // ---- P hi-fragments ----
        uint32_t aph[4][4];
        #pragma unroll
        for (int cc = 0; cc < 4; cc++) {
            aph[cc][0] = pack_bf2(__float2bfloat16(sv[2*cc][0]),   __float2bfloat16(sv[2*cc][1]));
            aph[cc][1] = pack_bf2(__float2bfloat16(sv[2*cc][2]),   __float2bfloat16(sv[2*cc][3]));
            aph[cc][2] = pack_bf2(__float2bfloat16(sv[2*cc+1][0]), __float2bfloat16(sv[2*cc+1][1]));
            aph[cc][3] = pack_bf2(__float2bfloat16(sv[2*cc+1][2]), __float2bfloat16(sv[2*cc+1][3]));
        }

        // ---- O += P @ V (3-pass split) ----
        #pragma unroll
        for (int pass = 0; pass < 3; pass++) {
            const int vro = (pass == 1) ? 64 : 0;
            #pragma unroll
            for (int cc = 0; cc < 4; cc++) {
                uint32_t a[4];
                if (pass < 2) {
                    a[0] = aph[cc][0]; a[1] = aph[cc][1]; a[2] = aph[cc][2]; a[3] = aph[cc][3];
                } else {
                    #pragma unroll
                    for (int q2 = 0; q2 < 2; q2++) {
                        float p0 = sv[2*cc][q2*2],   p1 = sv[2*cc][q2*2+1];
                        float p2 = sv[2*cc+1][q2*2], p3 = sv[2*cc+1][q2*2+1];
                        __nv_bfloat16 h0 = __float2bfloat16(p0), h1 = __float2bfloat16(p1);
                        __nv_bfloat16 h2 = __float2bfloat16(p2), h3 = __float2bfloat16(p3);
                        a[q2]     = pack_bf2(__float2bfloat16(p0 - __bfloat162float(h0)),
                                             __float2bfloat16(p1 - __bfloat162float(h1)));
                        a[q2 + 2] = pack_bf2(__float2bfloat16(p2 - __bfloat162float(h2)),
                                             __float2bfloat16(p3 - __bfloat162float(h3)));
                    }
                }
                #pragma unroll
                for (int nt2 = 0; nt2 < 4; nt2++) {
                    uint32_t bf[4];
                    const int d = vro + nt2 * 16 + brow;
                    const int chV = 2 * cc + hiB;
                    ldsm_x4(bf, vBase + d * 128 + (((chV ^ d) & 7) << 4));
                    mma16816(ov[nt2 * 2],     a, bf[0], bf[1]);
                    mma16816(ov[nt2 * 2 + 1], a, bf[2], bf[3]);
                }
            }
        }
        __syncthreads();
    }

    // ---- epilogue: normalize, write [hi|lo] A-layout for O-proj ----
    const float i0 = 1.f / l0, i1 = 1.f / l1;
    const size_t r0g = (size_t)(b * TT + qt * 128 + w * 16 + g);
    #pragma unroll
    for (int nt = 0; nt < 8; nt++) {
        const int dg = h * 64 + nt * 8 + tg * 2;
        #pragma unroll
        for (int half = 0; half < 2; half++) {
            const float x = ov[nt][half * 2]     * (half ? i1 : i0);
            const float y = ov[nt][half * 2 + 1] * (half ? i1 : i0);
            __nv_bfloat16 hx = __float2bfloat16(x), hy = __float2bfloat16(y);
            __nv_bfloat16 lx = __float2bfloat16(x - __bfloat162float(hx));
            __nv_bfloat16 ly = __float2bfloat16(y - __bfloat162float(hy));
            uint32_t* p = (uint32_t*)&g_ae[(r0g + half * 8) * KE + dg];
            p[0]   = pack_bf2(hx, hy);
            p[512] = pack_bf2(lx, ly);      // +1024 bf16
        }
    }
}

// ---------------- launch ----------------
extern "C" void kernel_launch(void* const* d_in, const int* in_sizes, int n_in,
                              void* d_out, int out_size)
{
    (void)in_sizes; (void)n_in; (void)out_size;
    const float* x  = (const float*)d_in[0];
    const float* wq = (const float*)d_in[1];
    const float* bq = (const float*)d_in[2];
    const float* wk = (const float*)d_in[3];
    const float* bk = (const float*)d_in[4];
    const float* wv = (const float*)d_in[5];
    const float* bv = (const float*)d_in[6];
    const float* wo = (const float*)d_in[7];
    const float* bo = (const float*)d_in[8];
    float* out = (float*)d_out;

    float* bkv;
    __nv_bfloat16 *xe, *ae, *weq, *wekv, *weo;
    cudaGetSymbolAddress((void**)&bkv,  g_bkv);
    cudaGetSymbolAddress((void**)&xe,   g_xe);
    cudaGetSymbolAddress((void**)&ae,   g_ae);
    cudaGetSymbolAddress((void**)&weq,  g_weq);
    cudaGetSymbolAddress((void**)&wekv, g_wekv);
    cudaGetSymbolAddress((void**)&weo,  g_weo);

    cudaFuncSetAttribute(mma_gemm,    cudaFuncAttributeMaxDynamicSharedMemorySize, GSM_TOTAL);
    cudaFuncSetAttribute(attn_kernel, cudaFuncAttributeMaxDynamicSharedMemorySize, AT_TOTAL);

    // merged prep: weight transposes + x split + rope + bias pack
    prep_kernel<<<2946, 256>>>(x, wq, wk, wv, wo, bk, bv);

    // Q proj -> g_qe (mode 0); K|V proj -> g_kve/g_vt (mode 1)
    mma_gemm<<<dim3(8, 32), 256, GSM_TOTAL>>>(xe, weq, bq, nullptr, 0, CC, 0);
    mma_gemm<<<dim3(4, 32), 256, GSM_TOTAL>>>(xe, wekv, bkv, nullptr, 0, 256, 1);

    attn_kernel<<<dim3(TT / 128, NH, BB), 256, AT_TOTAL>>>();

    // O proj -> fp32 out (mode 2)
    mma_gemm<<<dim3(8, 32), 256, GSM_TOTAL>>>(ae, weo, bo, out, CC, 0, 2);
}

// round 15
// speedup vs baseline: 3.0753x; 1.2160x over previous
#include <cuda_runtime.h>
#include <cuda_bf16.h>
#include <cstdint>
#include <cstddef>

// ---------------- problem constants ----------------
#define BB   2
#define TT   2048
#define CC   1024
#define NH   16
#define HD   64
#define MM   (BB * TT)        // 4096
#define KE   2048             // [hi(1024) | lo(1024)] operand layout
#define ROPE_C 0.14391156831212787f

// ---------------- scratch ----------------
__device__ float g_rope[TT * HD];
__device__ float g_bkv[512];
__device__ __nv_bfloat16 g_xe  [(size_t)MM * KE];     // x [hi|lo]
__device__ __nv_bfloat16 g_ae  [(size_t)MM * KE];     // attn out [hi|lo]
__device__ __nv_bfloat16 g_weq [(size_t)CC * KE];     // wq^T [hi|lo]
__device__ __nv_bfloat16 g_wekv[(size_t)512 * KE];    // [wk|wv]^T [hi|lo]
__device__ __nv_bfloat16 g_weo [(size_t)CC * KE];     // wo^T [hi|lo]
__device__ __nv_bfloat16 g_qe  [(size_t)MM * NH * 128];   // Q: [r][h][hi(64)|lo(64)], scaled
__device__ __nv_bfloat16 g_kve [(size_t)MM * 4 * 128];    // K: [r][kvh][hi|lo]
__device__ __nv_bfloat16 g_vt  [(size_t)BB * 4 * 128 * TT]; // V^T: [b][kvh][hi d|lo d][t]

// ---------------- PTX helpers (baseline ISA only) ----------------
__device__ __forceinline__ uint32_t smem_u32(const void* p) {
    uint32_t a;
    asm("{ .reg .u64 t; cvta.to.shared.u64 t, %1; cvt.u32.u64 %0, t; }" : "=r"(a) : "l"(p));
    return a;
}
__device__ __forceinline__ void ldsm_x4(uint32_t* r, uint32_t addr) {
    asm volatile("ldmatrix.sync.aligned.m8n8.x4.shared.b16 {%0,%1,%2,%3}, [%4];"
                 : "=r"(r[0]), "=r"(r[1]), "=r"(r[2]), "=r"(r[3]) : "r"(addr));
}
__device__ __forceinline__ void mma16816(float* d, const uint32_t* a, uint32_t b0, uint32_t b1) {
    asm volatile("mma.sync.aligned.m16n8k16.row.col.f32.bf16.bf16.f32 "
                 "{%0,%1,%2,%3}, {%4,%5,%6,%7}, {%8,%9}, {%0,%1,%2,%3};"
                 : "+f"(d[0]), "+f"(d[1]), "+f"(d[2]), "+f"(d[3])
                 : "r"(a[0]), "r"(a[1]), "r"(a[2]), "r"(a[3]), "r"(b0), "r"(b1));
}
__device__ __forceinline__ void cp16(uint32_t dst, const void* src) {
    asm volatile("cp.async.cg.shared.global [%0], [%1], 16;" :: "r"(dst), "l"(src));
}
#define CP_COMMIT() asm volatile("cp.async.commit_group;" ::: "memory")
#define CP_WAIT1()  asm volatile("cp.async.wait_group 1;" ::: "memory")
#define CP_WAIT0()  asm volatile("cp.async.wait_group 0;" ::: "memory")

__device__ __forceinline__ uint32_t pack_bf2(__nv_bfloat16 x, __nv_bfloat16 y) {
    union { __nv_bfloat162 h; uint32_t u; } c;
    c.h = __nv_bfloat162(x, y);
    return c.u;
}

// ---------------- merged prep kernel ----------------------------------------
__global__ void __launch_bounds__(256)
prep_kernel(const float* __restrict__ x,
            const float* __restrict__ wq, const float* __restrict__ wk,
            const float* __restrict__ wv, const float* __restrict__ wo,
            const float* __restrict__ bk, const float* __restrict__ bv)
{
    // row stride 68 floats = 272 B = multiple of 16 -> float4 ops aligned.
    __shared__ float sm[64][68];
    const int blk = blockIdx.x;
    const int tid = threadIdx.x;

    if (blk < 640) {
        const float* w; __nv_bfloat16* dst; int N, n_off, tt;
        if (blk < 256)      { w = wq; dst = g_weq;  N = 1024; n_off = 0;   tt = blk; }
        else if (blk < 320) { w = wk; dst = g_wekv; N = 256;  n_off = 0;   tt = blk - 256; }
        else if (blk < 384) { w = wv; dst = g_wekv; N = 256;  n_off = 256; tt = blk - 320; }
        else                { w = wo; dst = g_weo;  N = 1024; n_off = 0;   tt = blk - 384; }
        const int tiles_n = N >> 6;
        const int k0 = (tt / tiles_n) << 6;
        const int n0 = (tt % tiles_n) << 6;
        #pragma unroll
        for (int i = 0; i < 4; i++) {
            int e = tid + i * 256;
            int kk = e >> 4, seg = e & 15;
            *(float4*)&sm[kk][seg * 4] = *(const float4*)&w[(size_t)(k0 + kk) * N + n0 + seg * 4];
        }
        __syncthreads();
        const int n = tid >> 2, seg = tid & 3;
        __align__(16) __nv_bfloat16 hi16[16];
        __align__(16) __nv_bfloat16 lo16[16];
        #pragma unroll
        for (int j = 0; j < 16; j++) {
            float v = sm[seg * 16 + j][n];
            __nv_bfloat16 h = __float2bfloat16(v);
            hi16[j] = h;
            lo16[j] = __float2bfloat16(v - __bfloat162float(h));
        }
        __nv_bfloat16* base = dst + (size_t)(n_off + n0 + n) * KE + k0 + seg * 16;
        *(uint4*)(base)        = *(uint4*)&hi16[0];
        *(uint4*)(base + 8)    = *(uint4*)&hi16[8];
        *(uint4*)(base + 1024) = *(uint4*)&lo16[0];
        *(uint4*)(base + 1032) = *(uint4*)&lo16[8];
    } else if (blk < 2688) {
        const int idx = (blk - 640) * 2048 + tid * 8;
        const int r = idx >> 10, k = idx & 1023;
        float4 v0 = *(const float4*)&x[idx];
        float4 v1 = *(const float4*)&x[idx + 4];
        float f[8] = { v0.x, v0.y, v0.z, v0.w, v1.x, v1.y, v1.z, v1.w };
        __align__(16) __nv_bfloat16 hi[8];
        __align__(16) __nv_bfloat16 lo[8];
        #pragma unroll
        for (int j = 0; j < 8; j++) {
            hi[j] = __float2bfloat16(f[j]);
            lo[j] = __float2bfloat16(f[j] - __bfloat162float(hi[j]));
        }
        __nv_bfloat16* base = g_xe + (size_t)r * KE + k;
        *(uint4*)(base)        = *(uint4*)&hi[0];
        *(uint4*)(base + 1024) = *(uint4*)&lo[0];
    } else if (blk < 2944) {
        const int id = (blk - 2688) * 256 + tid;
        const int t = id >> 5, p = id & 31;
        float inv = expf(-(float)(2 * p) * ROPE_C);
        float sn, cs;
        sincosf((float)t * inv, &sn, &cs);
        g_rope[t * HD + 2 * p]     = cs;
        g_rope[t * HD + 2 * p + 1] = sn;
    } else {
        const int i = (blk - 2944) * 256 + tid;
        g_bkv[i] = (i < 256) ? bk[i] : bv[i - 256];
    }
}

// ---------------- HMMA GEMM: 128x128 tile, 8 warps, BK=64 -------------------
// cp.async triple-buffered staging, one __syncthreads per chunk.
// 3 logical passes over [hi|lo] operands: (Ahi,Whi), (Ahi,Wlo), (Alo,Whi).
// mode 0: Q proj -> g_qe;  mode 1: KV proj -> g_kve/g_vt;  mode 2: O proj -> fp32 C
#define GSM_TOTAL (3 * 32768)

__device__ __forceinline__ void pass_offsets(int it, int& ka, int& kb) {
    const int pass = it >> 4, kc = it & 15;
    ka = ((pass == 2) ? 1024 : 0) + kc * 64;
    kb = ((pass == 1) ? 1024 : 0) + kc * 64;
}

__device__ __forceinline__ void stage_async(uint32_t dstA, uint32_t dstB,
                                            const __nv_bfloat16* Ap, const __nv_bfloat16* Wp,
                                            int ka, int kb, int tid)
{
    #pragma unroll
    for (int i = 0; i < 4; i++) {
        int e   = tid + i * 256;
        int row = e >> 3, ch = e & 7;
        uint32_t sw = row * 128 + ((ch ^ (row & 7)) << 4);
        cp16(dstA + sw, Ap + (size_t)row * KE + ka + ch * 8);
        cp16(dstB + sw, Wp + (size_t)row * KE + kb + ch * 8);
    }
}

// split: blocks with col0 < split use W0/b0 (mode = mode0_val); else W1/b1 (mode 1).
__global__ void __launch_bounds__(256, 2)
mma_gemm(const __nv_bfloat16* __restrict__ A,
         const __nv_bfloat16* __restrict__ W0, const float* __restrict__ b0,
         const __nv_bfloat16* __restrict__ W1, const float* __restrict__ b1,
         float* __restrict__ C, int ldc, int split, int mode0_val)
{
    extern __shared__ char smem[];
    const uint32_t sb = smem_u32(smem);
    // buffer s: A at sb + s*32768, B at sb + s*32768 + 16384

    const int tid  = threadIdx.x;
    const int wid  = tid >> 5;
    const int lane = tid & 31;
    const int warpRow = wid & 1;
    const int warpCol = wid >> 1;
    const int row0 = blockIdx.y * 128;
    const int gcol0 = blockIdx.x * 128;

    const __nv_bfloat16* W; const float* bias; int wc0, mode;
    if (gcol0 < split) { W = W0; bias = b0; wc0 = gcol0;         mode = mode0_val; }
    else               { W = W1; bias = b1; wc0 = gcol0 - split; mode = 1; }

    const __nv_bfloat16* Ap = A + (size_t)row0 * KE;
    const __nv_bfloat16* Wp = W + (size_t)wc0 * KE;

    const int rx   = lane & 7;
    const int rowA = warpRow * 64 + (lane & 7) + ((lane >> 3) & 1) * 8;
    const int hiA  = (lane >> 4) & 1;
    const int rowB = warpCol * 32 + (lane & 7) + ((lane >> 4) & 1) * 8;
    const int hiB  = (lane >> 3) & 1;

    float acc[4][4][4];
    #pragma unroll
    for (int mi = 0; mi < 4; mi++)
        #pragma unroll
        for (int nb = 0; nb < 4; nb++)
            #pragma unroll
            for (int q = 0; q < 4; q++) acc[mi][nb][q] = 0.f;

    const int NIT = 48;    // 3 passes x 16 chunks
    {
        int ka, kb2; pass_offsets(0, ka, kb2);
        stage_async(sb, sb + 16384, Ap, Wp, ka, kb2, tid);
        CP_COMMIT();
    }

    for (int it = 0; it < NIT; it++) {
        if (it + 1 < NIT) {
            const uint32_t nb_ = sb + ((it + 1) % 3) * 32768;
            int ka, kb2; pass_offsets(it + 1, ka, kb2);
            stage_async(nb_, nb_ + 16384, Ap, Wp, ka, kb2, tid);
            CP_COMMIT();
            CP_WAIT1();
        } else {
            CP_WAIT0();
        }
        __syncthreads();

        const uint32_t bufc = sb + (it % 3) * 32768;
        const uint32_t aBase = bufc + rowA * 128;
        const uint32_t bBase = bufc + 16384 + rowB * 128;
        #pragma unroll
        for (int kk = 0; kk < 4; kk++) {
            uint32_t a[4][4], b[2][4];
            #pragma unroll
            for (int mi = 0; mi < 4; mi++)
                ldsm_x4(a[mi], aBase + mi * 2048 + ((((kk * 2 + hiA) ^ rx)) << 4));
            #pragma unroll
            for (int nj = 0; nj < 2; nj++)
                ldsm_x4(b[nj], bBase + nj * 2048 + ((((kk * 2 + hiB) ^ rx)) << 4));
            #pragma unroll
            for (int mi = 0; mi < 4; mi++) {
                mma16816(acc[mi][0], a[mi], b[0][0], b[0][1]);
                mma16816(acc[mi][1], a[mi], b[0][2], b[0][3]);
                mma16816(acc[mi][2], a[mi], b[1][0], b[1][1]);
                mma16816(acc[mi][3], a[mi], b[1][2], b[1][3]);
            }
        }
    }

    const int g  = lane >> 2;
    const int tg = lane & 3;
    #pragma unroll
    for (int mi = 0; mi < 4; mi++) {
        #pragma unroll
        for (int nb = 0; nb < 4; nb++) {
            const int col = wc0 + warpCol * 32 + nb * 8 + tg * 2;   // local col in W
            const float bx = bias[col], by = bias[col + 1];
            const bool rp = (mode == 0) || (mode == 1 && col < 256);
            #pragma unroll
            for (int half = 0; half < 2; half++) {
                const int r = row0 + warpRow * 64 + mi * 16 + g + half * 8;
                float x = acc[mi][nb][half * 2]     + bx;
                float y = acc[mi][nb][half * 2 + 1] + by;
                if (rp) {
                    const int t = r & (TT - 1);
                    float2 cn = *(const float2*)&g_rope[t * HD + (col & (HD - 1))];
                    float e = x, o = y;
                    x = e * cn.x - o * cn.y;
                    y = e * cn.y + o * cn.x;
                }
                if (mode == 2) {
                    *(float2*)(C + (size_t)r * ldc + col) = make_float2(x, y);
                } else if (mode == 0) {
                    x *= 0.125f; y *= 0.125f;
                    __nv_bfloat16 hx = __float2bfloat16(x), hy = __float2bfloat16(y);
                    __nv_bfloat16 lx = __float2bfloat16(x - __bfloat162float(hx));
                    __nv_bfloat16 ly = __float2bfloat16(y - __bfloat162float(hy));
                    const int h = col >> 6, d = col & 63;
                    uint32_t* p = (uint32_t*)&g_qe[((size_t)r * NH + h) * 128 + d];
                    p[0]  = pack_bf2(hx, hy);
                    p[32] = pack_bf2(lx, ly);
                } else {
                    __nv_bfloat16 hx = __float2bfloat16(x), hy = __float2bfloat16(y);
                    __nv_bfloat16 lx = __float2bfloat16(x - __bfloat162float(hx));
                    __nv_bfloat16 ly = __float2bfloat16(y - __bfloat162float(hy));
                    if (col < 256) {
                        const int h = col >> 6, d = col & 63;
                        uint32_t* p = (uint32_t*)&g_kve[((size_t)r * 4 + h) * 128 + d];
                        p[0]  = pack_bf2(hx, hy);
                        p[32] = pack_bf2(lx, ly);
                    } else {
                        const int cv = col - 256, h = cv >> 6, d = cv & 63;
                        const int bb = r >> 11, t = r & (TT - 1);
                        __nv_bfloat16* p = &g_vt[(((size_t)(bb * 4 + h) * 128) + d) * TT + t];
                        p[0]        = hx;
                        p[TT]       = hy;
                        p[64 * TT]  = lx;
                        p[65 * TT]  = ly;
                    }
                }
            }
        }
    }
}

// ---------------- tensor-core flash attention (unchanged from R14) ----------
#define AT_QS   0
#define AT_K0   32768
#define AT_V0   65536
#define AT_TOTAL 98304

__device__ __forceinline__ void load_kv_chunk(uint32_t sb, int buf, int b, int kvh,
                                              int t0, int tid)
{
    const __nv_bfloat16* kg = &g_kve[((size_t)(b * TT + t0) * 4 + kvh) * 128];
    const uint32_t kdst = sb + AT_K0 + buf * 16384;
    #pragma unroll
    for (int i = 0; i < 4; i++) {
        int e = tid + i * 256, c = e >> 4, ch = e & 15;
        cp16(kdst + c * 256 + (((ch & 8) | ((ch ^ c) & 7)) << 4), kg + (size_t)c * 512 + ch * 8);
    }
    const __nv_bfloat16* vg = &g_vt[(size_t)(b * 4 + kvh) * 128 * TT + t0];
    const uint32_t vdst = sb + AT_V0 + buf * 16384;
    #pragma unroll
    for (int i = 0; i < 4; i++) {
        int e = tid + i * 256, d = e >> 3, ch = e & 7;
        cp16(vdst + d * 128 + (((ch ^ d) & 7) << 4), vg + (size_t)d * TT + ch * 8);
    }
}

__global__ void __launch_bounds__(256, 2)
attn_kernel()
{
    extern __shared__ char smem[];
    const uint32_t sb = smem_u32(smem);

    const int b  = blockIdx.z;
    const int h  = blockIdx.y;
    const int qt = gridDim.x - 1 - blockIdx.x;   // heavy tiles first
    const int kvh = h >> 2;
    const int tid  = threadIdx.x;
    const int w    = tid >> 5;
    const int lane = tid & 31;
    const int g    = lane >> 2;
    const int tg   = lane & 3;

    {
        const __nv_bfloat16* qg = &g_qe[((size_t)(b * TT + qt * 128) * NH + h) * 128];
        #pragma unroll
        for (int i = 0; i < 8; i++) {
            int e = tid + i * 256, r = e >> 4, ch = e & 15;
            cp16(sb + AT_QS + r * 256 + (((ch & 8) | ((ch ^ r) & 7)) << 4),
                 qg + (size_t)r * (NH * 128) + ch * 8);
        }
    }
    CP_COMMIT();
    load_kv_chunk(sb, 0, b, kvh, 0, tid);
    CP_COMMIT();

    const int qrow = w * 16 + (lane & 7) + ((lane >> 3) & 1) * 8;
    const int hiA  = (lane >> 4) & 1;
    const int brow = (lane & 7) + ((lane >> 4) & 1) * 8;
    const int hiB  = (lane >> 3) & 1;
    const uint32_t aBase = sb + AT_QS + qrow * 256;

    float m0 = -3.0e38f, m1 = -3.0e38f, l0 = 0.f, l1 = 0.f;
    float ov[8][4];
    #pragma unroll
    for (int nt = 0; nt < 8; nt++)
        #pragma unroll
        for (int q = 0; q < 4; q++) ov[nt][q] = 0.f;

    const int jend = 2 * qt + 1;
    for (int jt = 0; jt <= jend; jt++) {
        if (jt < jend) { load_kv_chunk(sb, (jt + 1) & 1, b, kvh, (jt + 1) * 64, tid); CP_COMMIT(); CP_WAIT1(); }
        else CP_WAIT0();
        __syncthreads();

        const int buf = jt & 1;
        const uint32_t kBase = sb + AT_K0 + buf * 16384;
        const uint32_t vBase = sb + AT_V0 + buf * 16384;

        float sv[8][4];
        #pragma unroll
        for (int nt = 0; nt < 8; nt++)
            #pragma unroll
            for (int q = 0; q < 4; q++) sv[nt][q] = 0.f;

        #pragma unroll
        for (int pass = 0; pass < 3; pass++) {
            const int qo = (pass == 2) ? 8 : 0;
            const int ko = (pass == 1) ? 8 : 0;
            #pragma unroll
            for (int kc = 0; kc < 4; kc++) {
                uint32_t a[4];
                const int chA = qo + 2 * kc + hiA;
                ldsm_x4(a, aBase + (((chA & 8) | ((chA ^ qrow) & 7)) << 4));
                #pragma unroll
                for (int nt2 = 0; nt2 < 4; nt2++) {
                    uint32_t bf[4];
                    const int c = nt2 * 16 + brow;
                    const int chB = ko + 2 * kc + hiB;
                    ldsm_x4(bf, kBase + c * 256 + (((chB & 8) | ((chB ^ c) & 7)) << 4));
                    mma16816(sv[nt2 * 2],     a, bf[0], bf[1]);
                    mma16816(sv[nt2 * 2 + 1], a, bf[2], bf[3]);
                }
            }
        }

        const int kc0 = jt * 64;
        if (kc0 + 63 > qt * 128 + w * 16) {
            #pragma unroll
            for (int nt = 0; nt < 8; nt++)
                #pragma unroll
                for (int q = 0; q < 4; q++) {
                    const int row = qt * 128 + w * 16 + g + 8 * (q >> 1);
                    const int col = kc0 + nt * 8 + tg * 2 + (q & 1);
                    if (col > row) sv[nt][q] = -1.0e30f;
                }
        }

        float mx0 = -3.0e38f, mx1 = -3.0e38f;
        #pragma unroll
        for (int nt = 0; nt < 8; nt++) {
            mx0 = fmaxf(mx0, fmaxf(sv[nt][0], sv[nt][1]));
            mx1 = fmaxf(mx1, fmaxf(sv[nt][2], sv[nt][3]));
        }
        mx0 = fmaxf(mx0, __shfl_xor_sync(0xffffffffu, mx0, 1));
        mx0 = fmaxf(mx0, __shfl_xor_sync(0xffffffffu, mx0, 2));
        mx1 = fmaxf(mx1, __shfl_xor_sync(0xffffffffu, mx1, 1));
        mx1 = fmaxf(mx1, __shfl_xor_sync(0xffffffffu, mx1, 2));
        const float mn0 = fmaxf(m0, mx0), mn1 = fmaxf(m1, mx1);
        const float al0 = __expf(m0 - mn0), al1 = __expf(m1 - mn1);
        float rs0 = 0.f, rs1 = 0.f;
        #pragma unroll
        for (int nt = 0; nt < 8; nt++) {
            sv[nt][0] = __expf(sv[nt][0] - mn0); rs0 += sv[nt][0];
            sv[nt][1] = __expf(sv[nt][1] - mn0); rs0 += sv[nt][1];
            sv[nt][2] = __expf(sv[nt][2] - mn1); rs1 += sv[nt][2];
            sv[nt][3] = __expf(sv[nt][3] - mn1); rs1 += sv[nt][3];
        }
        rs0 += __shfl_xor_sync(0xffffffffu, rs0, 1);
        rs0 += __shfl_xor_sync(0xffffffffu, rs0, 2);
        rs1 += __shfl_xor_sync(0xffffffffu, rs1, 1);
        rs1 += __shfl_xor_sync(0xffffffffu, rs1, 2);
        l0 = l0 * al0 + rs0; l1 = l1 * al1 + rs1;
        m0 = mn0; m1 = mn1;
        #pragma unroll
        for (int nt = 0; nt < 8; nt++) {
            ov[nt][0] *= al0; ov[nt][1] *= al0;
            ov[nt][2] *= al1; ov[nt][3] *= al1;
        }

        uint32_t aph[4][4];
        #pragma unroll
        for (int cc = 0; cc < 4; cc++) {
            aph[cc][0] = pack_bf2(__float2bfloat16(sv[2*cc][0]),   __float2bfloat16(sv[2*cc][1]));
            aph[cc][1] = pack_bf2(__float2bfloat16(sv[2*cc][2]),   __float2bfloat16(sv[2*cc][3]));
            aph[cc][2] = pack_bf2(__float2bfloat16(sv[2*cc+1][0]), __float2bfloat16(sv[2*cc+1][1]));
            aph[cc][3] = pack_bf2(__float2bfloat16(sv[2*cc+1][2]), __float2bfloat16(sv[2*cc+1][3]));
        }

        #pragma unroll
        for (int pass = 0; pass < 3; pass++) {
            const int vro = (pass == 1) ? 64 : 0;
            #pragma unroll
            for (int cc = 0; cc < 4; cc++) {
                uint32_t a[4];
                if (pass < 2) {
                    a[0] = aph[cc][0]; a[1] = aph[cc][1]; a[2] = aph[cc][2]; a[3] = aph[cc][3];
                } else {
                    #pragma unroll
                    for (int q2 = 0; q2 < 2; q2++) {
                        float p0 = sv[2*cc][q2*2],   p1 = sv[2*cc][q2*2+1];
                        float p2 = sv[2*cc+1][q2*2], p3 = sv[2*cc+1][q2*2+1];
                        __nv_bfloat16 h0 = __float2bfloat16(p0), h1 = __float2bfloat16(p1);
                        __nv_bfloat16 h2 = __float2bfloat16(p2), h3 = __float2bfloat16(p3);
                        a[q2]     = pack_bf2(__float2bfloat16(p0 - __bfloat162float(h0)),
                                             __float2bfloat16(p1 - __bfloat162float(h1)));
                        a[q2 + 2] = pack_bf2(__float2bfloat16(p2 - __bfloat162float(h2)),
                                             __float2bfloat16(p3 - __bfloat162float(h3)));
                    }
                }
                #pragma unroll
                for (int nt2 = 0; nt2 < 4; nt2++) {
                    uint32_t bf[4];
                    const int d = vro + nt2 * 16 + brow;
                    const int chV = 2 * cc + hiB;
                    ldsm_x4(bf, vBase + d * 128 + (((chV ^ d) & 7) << 4));
                    mma16816(ov[nt2 * 2],     a, bf[0], bf[1]);
                    mma16816(ov[nt2 * 2 + 1], a, bf[2], bf[3]);
                }
            }
        }
        __syncthreads();
    }

    const float i0 = 1.f / l0, i1 = 1.f / l1;
    const size_t r0g = (size_t)(b * TT + qt * 128 + w * 16 + g);
    #pragma unroll
    for (int nt = 0; nt < 8; nt++) {
        const int dg = h * 64 + nt * 8 + tg * 2;
        #pragma unroll
        for (int half = 0; half < 2; half++) {
            const float x = ov[nt][half * 2]     * (half ? i1 : i0);
            const float y = ov[nt][half * 2 + 1] * (half ? i1 : i0);
            __nv_bfloat16 hx = __float2bfloat16(x), hy = __float2bfloat16(y);
            __nv_bfloat16 lx = __float2bfloat16(x - __bfloat162float(hx));
            __nv_bfloat16 ly = __float2bfloat16(y - __bfloat162float(hy));
            uint32_t* p = (uint32_t*)&g_ae[(r0g + half * 8) * KE + dg];
            p[0]   = pack_bf2(hx, hy);
            p[512] = pack_bf2(lx, ly);
        }
    }
}

// ---------------- launch ----------------
extern "C" void kernel_launch(void* const* d_in, const int* in_sizes, int n_in,
                              void* d_out, int out_size)
{
    (void)in_sizes; (void)n_in; (void)out_size;
    const float* x  = (const float*)d_in[0];
    const float* wq = (const float*)d_in[1];
    const float* bq = (const float*)d_in[2];
    const float* wk = (const float*)d_in[3];
    const float* bk = (const float*)d_in[4];
    const float* wv = (const float*)d_in[5];
    const float* bv = (const float*)d_in[6];
    const float* wo = (const float*)d_in[7];
    const float* bo = (const float*)d_in[8];
    float* out = (float*)d_out;

    float* bkv;
    __nv_bfloat16 *xe, *ae, *weq, *wekv, *weo;
    cudaGetSymbolAddress((void**)&bkv,  g_bkv);
    cudaGetSymbolAddress((void**)&xe,   g_xe);
    cudaGetSymbolAddress((void**)&ae,   g_ae);
    cudaGetSymbolAddress((void**)&weq,  g_weq);
    cudaGetSymbolAddress((void**)&wekv, g_wekv);
    cudaGetSymbolAddress((void**)&weo,  g_weo);

    cudaFuncSetAttribute(mma_gemm,    cudaFuncAttributeMaxDynamicSharedMemorySize, GSM_TOTAL);
    cudaFuncSetAttribute(attn_kernel, cudaFuncAttributeMaxDynamicSharedMemorySize, AT_TOTAL);

    // merged prep: weight transposes + x split + rope + bias pack
    prep_kernel<<<2946, 256>>>(x, wq, wk, wv, wo, bk, bv);

    // fused Q + KV projection: cols [0,1024) -> Q (mode 0), [1024,1536) -> KV (mode 1)
    mma_gemm<<<dim3(12, 32), 256, GSM_TOTAL>>>(xe, weq, bq, wekv, bkv, nullptr, 0, 1024, 0);

    attn_kernel<<<dim3(TT / 128, NH, BB), 256, AT_TOTAL>>>();

    // O proj -> fp32 out (mode 2)
    mma_gemm<<<dim3(8, 32), 256, GSM_TOTAL>>>(ae, weo, bo, weo, bo, out, CC, 1024, 2);
}